// round 1
// baseline (speedup 1.0000x reference)
#include <cuda_runtime.h>
#include <math.h>

// ---------------- scratch (no allocations allowed) ----------------
__device__ float g_hfc[4 * 4096];   // FC output, (4, 4096)
__device__ float g_seq[2 * 4096];   // conv-chain output, flat 8192 = (2,4,1024) view

// ---------------- Kernel 1: FC  h = leaky(x @ W^T + b) ----------------
// x: (4, 40960), W: (4096, 40960). 8 W-rows per block, 512 blocks.
// x is loaded once per block (L2-hot), W streams from HBM exactly once.
__global__ __launch_bounds__(256) void fc_kernel(const float* __restrict__ x,
                                                 const float* __restrict__ W,
                                                 const float* __restrict__ bias) {
    const int row0 = blockIdx.x * 8;
    const int tid = threadIdx.x;

    float acc[8][4];
#pragma unroll
    for (int r = 0; r < 8; r++)
#pragma unroll
        for (int b = 0; b < 4; b++) acc[r][b] = 0.f;

    const float4* __restrict__ x4 = (const float4*)x;  // b*10240 + c

    for (int c = tid; c < 10240; c += 256) {
        float4 xv[4];
#pragma unroll
        for (int b = 0; b < 4; b++) xv[b] = x4[b * 10240 + c];
#pragma unroll
        for (int r = 0; r < 8; r++) {
            const float4 w = ((const float4*)(W + (size_t)(row0 + r) * 40960))[c];
#pragma unroll
            for (int b = 0; b < 4; b++) {
                acc[r][b] += w.x * xv[b].x;
                acc[r][b] += w.y * xv[b].y;
                acc[r][b] += w.z * xv[b].z;
                acc[r][b] += w.w * xv[b].w;
            }
        }
    }

    // warp reduce
#pragma unroll
    for (int r = 0; r < 8; r++)
#pragma unroll
        for (int b = 0; b < 4; b++)
#pragma unroll
            for (int off = 16; off; off >>= 1)
                acc[r][b] += __shfl_down_sync(0xffffffffu, acc[r][b], off);

    __shared__ float sred[8][8][4];  // [warp][r][b]
    const int lane = tid & 31, wid = tid >> 5;
    if (lane == 0) {
#pragma unroll
        for (int r = 0; r < 8; r++)
#pragma unroll
            for (int b = 0; b < 4; b++) sred[wid][r][b] = acc[r][b];
    }
    __syncthreads();

    if (tid < 32) {
        const int r = tid >> 2, b = tid & 3;
        float s = 0.f;
#pragma unroll
        for (int w = 0; w < 8; w++) s += sred[w][r][b];
        s += bias[row0 + r];
        s = (s >= 0.f) ? s : 0.4f * s;               // LeakyReLU(0.4)
        g_hfc[b * 4096 + row0 + r] = s;
    }
}

// ---------------- Kernel 2: conv chain + instance norm ----------------
template <int CIN, int HIN, int WIN, int COUT, int HOUT, int WOUT, int STRIDE>
__device__ __forceinline__ void conv_in(const float* __restrict__ in, float* __restrict__ out,
                                        const float* __restrict__ wgt,
                                        const float* __restrict__ bias,
                                        float* smean, float* srstd, int tid) {
    const int S = HOUT * WOUT;
    for (int idx = tid; idx < COUT * S; idx += 256) {
        const int c = idx / S;
        const int rem = idx - c * S;
        const int y = rem / WOUT;
        const int xx = rem - y * WOUT;
        float acc = bias[c];
        for (int ic = 0; ic < CIN; ic++) {
            const float* __restrict__ ip = in + ic * HIN * WIN;
            const float* __restrict__ wp = wgt + (c * CIN + ic) * 9;
#pragma unroll
            for (int dy = 0; dy < 3; dy++) {
                const int yy = y * STRIDE + dy - 1;
                if (yy < 0 || yy >= HIN) continue;
#pragma unroll
                for (int dx = 0; dx < 3; dx++) {
                    const int xs = xx * STRIDE + dx - 1;
                    if (xs < 0 || xs >= WIN) continue;
                    acc += ip[yy * WIN + xs] * wp[dy * 3 + dx];
                }
            }
        }
        out[idx] = acc;
    }
    __syncthreads();

    // instance norm per channel: one warp per channel (strided over 8 warps)
    const int wid = tid >> 5, lane = tid & 31;
    for (int c = wid; c < COUT; c += 8) {
        float s = 0.f, s2 = 0.f;
        for (int e = lane; e < S; e += 32) {
            const float v = out[c * S + e];
            s += v;
            s2 += v * v;
        }
#pragma unroll
        for (int off = 16; off; off >>= 1) {
            s += __shfl_down_sync(0xffffffffu, s, off);
            s2 += __shfl_down_sync(0xffffffffu, s2, off);
        }
        if (lane == 0) {
            const float m = s / (float)S;
            const float var = s2 / (float)S - m * m;
            smean[c] = m;
            srstd[c] = rsqrtf(var + 1e-5f);
        }
    }
    __syncthreads();
    for (int idx = tid; idx < COUT * S; idx += 256) {
        const int c = idx / S;
        out[idx] = (out[idx] - smean[c]) * srstd[c];
    }
    __syncthreads();
}

__global__ __launch_bounds__(256) void conv_chain_kernel(
    const float* __restrict__ w0, const float* __restrict__ b0,
    const float* __restrict__ w1, const float* __restrict__ b1,
    const float* __restrict__ w2, const float* __restrict__ b2,
    const float* __restrict__ w3, const float* __restrict__ b3,
    const float* __restrict__ w4, const float* __restrict__ b4,
    const float* __restrict__ w5, const float* __restrict__ b5) {
    __shared__ float bufA[4096];
    __shared__ float bufB[4096];
    __shared__ float smean[64];
    __shared__ float srstd[64];
    const int n = blockIdx.x;   // one block per batch element
    const int tid = threadIdx.x;

    for (int i = tid; i < 4096; i += 256) bufA[i] = g_hfc[n * 4096 + i];
    __syncthreads();

    conv_in<1, 4, 1024, 1, 4, 1024, 1>(bufA, bufB, w0, b0, smean, srstd, tid);
    conv_in<1, 4, 1024, 4, 2, 512, 2>(bufB, bufA, w1, b1, smean, srstd, tid);
    conv_in<4, 2, 512, 8, 1, 256, 2>(bufA, bufB, w2, b2, smean, srstd, tid);
    conv_in<8, 1, 256, 16, 1, 128, 2>(bufB, bufA, w3, b3, smean, srstd, tid);
    conv_in<16, 1, 128, 32, 1, 64, 2>(bufA, bufB, w4, b4, smean, srstd, tid);
    conv_in<32, 1, 64, 64, 1, 32, 2>(bufB, bufA, w5, b5, smean, srstd, tid);

    // layer-5 output (64 ch x 32) -> flat seq buffer
    for (int i = tid; i < 2048; i += 256) g_seq[n * 2048 + i] = bufA[i];
}

// ---------------- Kernel 3: 64-layer tanh RNN + output head ----------------
// seq view: seq[t][b][i] = g_seq[t*4096 + b*1024 + i]
// thread = (b = tid>>6, j = tid&63)
__global__ __launch_bounds__(256) void rnn_kernel(
    const float* __restrict__ W_ih0, const float* __restrict__ b_ih0,
    const float* __restrict__ W_ihr, const float* __restrict__ b_ihr,
    const float* __restrict__ W_hh, const float* __restrict__ b_hh,
    const float* __restrict__ W_out, const float* __restrict__ b_out,
    float* __restrict__ out) {
    __shared__ float s[2][4][64];
    __shared__ float hb[4][64];
    const int tid = threadIdx.x;
    const int b = tid >> 6;
    const int j = tid & 63;

    // ---- layer 0: W_ih0 is (64,1024) ----
    float pre0, pre1;
    {
        const float4* __restrict__ w4 = (const float4*)(W_ih0 + j * 1024);
        float a0 = 0.f, a1 = 0.f;
        const float4* __restrict__ x0 = (const float4*)(g_seq + 0 * 4096 + b * 1024);
        const float4* __restrict__ x1 = (const float4*)(g_seq + 1 * 4096 + b * 1024);
        for (int i = 0; i < 256; i++) {
            const float4 w = w4[i];
            const float4 v0 = x0[i];
            const float4 v1 = x1[i];
            a0 += w.x * v0.x + w.y * v0.y + w.z * v0.z + w.w * v0.w;
            a1 += w.x * v1.x + w.y * v1.y + w.z * v1.z + w.w * v1.w;
        }
        const float bi = b_ih0[j];
        pre0 = a0 + bi;
        pre1 = a1 + bi;
    }
    {
        const float bh = b_hh[j];            // layer 0 row of b_hh
        const float h1 = tanhf(pre0 + bh);   // h0 = 0 -> recurrent term vanishes
        hb[b][j] = h1;
        s[0][b][j] = h1;
        __syncthreads();
        float a = pre1 + bh;
        const float4* __restrict__ Wh4 = (const float4*)(W_hh + j * 64);
#pragma unroll
        for (int i4 = 0; i4 < 16; i4++) {
            const float4 w = Wh4[i4];
            a += w.x * hb[b][4 * i4 + 0] + w.y * hb[b][4 * i4 + 1] +
                 w.z * hb[b][4 * i4 + 2] + w.w * hb[b][4 * i4 + 3];
        }
        s[1][b][j] = tanhf(a);
        __syncthreads();
    }

    // ---- layers 1..63 ----
    for (int l = 1; l < 64; l++) {
        const float4* __restrict__ Wi4 = (const float4*)(W_ihr + (size_t)(l - 1) * 4096 + j * 64);
        const float bi = b_ihr[(l - 1) * 64 + j];
        float p0 = bi, p1 = bi;
#pragma unroll
        for (int i4 = 0; i4 < 16; i4++) {
            const float4 w = Wi4[i4];
            p0 += w.x * s[0][b][4 * i4 + 0] + w.y * s[0][b][4 * i4 + 1] +
                  w.z * s[0][b][4 * i4 + 2] + w.w * s[0][b][4 * i4 + 3];
            p1 += w.x * s[1][b][4 * i4 + 0] + w.y * s[1][b][4 * i4 + 1] +
                  w.z * s[1][b][4 * i4 + 2] + w.w * s[1][b][4 * i4 + 3];
        }
        __syncthreads();  // all reads of old s done
        const float bh = b_hh[l * 64 + j];
        const float h1 = tanhf(p0 + bh);
        hb[b][j] = h1;
        s[0][b][j] = h1;
        __syncthreads();
        float a = p1 + bh;
        const float4* __restrict__ Wh4 = (const float4*)(W_hh + (size_t)l * 4096 + j * 64);
#pragma unroll
        for (int i4 = 0; i4 < 16; i4++) {
            const float4 w = Wh4[i4];
            a += w.x * hb[b][4 * i4 + 0] + w.y * hb[b][4 * i4 + 1] +
                 w.z * hb[b][4 * i4 + 2] + w.w * hb[b][4 * i4 + 3];
        }
        s[1][b][j] = tanhf(a);
        __syncthreads();
    }

    // ---- output head: (2,4,34) = 272 floats, leaky(seq @ W_out^T + b_out) ----
    for (int idx = tid; idx < 272; idx += 256) {
        const int t = idx / 136;
        const int rem = idx - t * 136;
        const int bb = rem / 34;
        const int o = rem - bb * 34;
        float a = b_out[o];
        const float4* __restrict__ Wo4 = (const float4*)(W_out + o * 64);
#pragma unroll
        for (int i4 = 0; i4 < 16; i4++) {
            const float4 w = Wo4[i4];
            a += w.x * s[t][bb][4 * i4 + 0] + w.y * s[t][bb][4 * i4 + 1] +
                 w.z * s[t][bb][4 * i4 + 2] + w.w * s[t][bb][4 * i4 + 3];
        }
        out[idx] = (a >= 0.f) ? a : 0.4f * a;
    }
}

// ---------------- launch ----------------
extern "C" void kernel_launch(void* const* d_in, const int* in_sizes, int n_in,
                              void* d_out, int out_size) {
    const float* x     = (const float*)d_in[0];
    const float* W_fc  = (const float*)d_in[1];
    const float* b_fc  = (const float*)d_in[2];
    const float* w0    = (const float*)d_in[3];
    const float* b0    = (const float*)d_in[4];
    const float* w1    = (const float*)d_in[5];
    const float* b1    = (const float*)d_in[6];
    const float* w2    = (const float*)d_in[7];
    const float* b2    = (const float*)d_in[8];
    const float* w3    = (const float*)d_in[9];
    const float* b3    = (const float*)d_in[10];
    const float* w4    = (const float*)d_in[11];
    const float* b4    = (const float*)d_in[12];
    const float* w5    = (const float*)d_in[13];
    const float* b5    = (const float*)d_in[14];
    const float* W_ih0 = (const float*)d_in[15];
    const float* b_ih0 = (const float*)d_in[16];
    const float* W_ihr = (const float*)d_in[17];
    const float* b_ihr = (const float*)d_in[18];
    const float* W_hh  = (const float*)d_in[19];
    const float* b_hh  = (const float*)d_in[20];
    const float* W_out = (const float*)d_in[21];
    const float* b_out = (const float*)d_in[22];
    float* out = (float*)d_out;

    fc_kernel<<<512, 256>>>(x, W_fc, b_fc);
    conv_chain_kernel<<<4, 256>>>(w0, b0, w1, b1, w2, b2, w3, b3, w4, b4, w5, b5);
    rnn_kernel<<<1, 256>>>(W_ih0, b_ih0, W_ihr, b_ihr, W_hh, b_hh, W_out, b_out, out);
}

// round 3
// speedup vs baseline: 3.1076x; 3.1076x over previous
#include <cuda_runtime.h>
#include <math.h>

// ---------------- scratch (no allocations allowed) ----------------
__device__ float g_hfc[4 * 4096];       // FC output, (4, 4096)
__device__ float g_seq[2 * 4096];       // conv-chain output (T=2,B=4,1024)
__device__ float g_pre[2 * 4 * 64];     // layer-0 input projection (+b_ih0)
__device__ float g_y[64 * 2 * 4 * 64];  // per-layer outputs
__device__ volatile int g_flag[64 * 2]; // pipeline flags

// ---------------- Kernel 1: FC  h = leaky(x @ W^T + b) ----------------
__global__ __launch_bounds__(256) void fc_kernel(const float* __restrict__ x,
                                                 const float* __restrict__ W,
                                                 const float* __restrict__ bias) {
    const int row0 = blockIdx.x * 8;
    const int tid = threadIdx.x;

    float acc[8][4];
#pragma unroll
    for (int r = 0; r < 8; r++)
#pragma unroll
        for (int b = 0; b < 4; b++) acc[r][b] = 0.f;

    const float4* __restrict__ x4 = (const float4*)x;  // b*10240 + c

    for (int c = tid; c < 10240; c += 512) {
        const int c2 = c + 256;
        float4 xv[4], xv2[4];
#pragma unroll
        for (int b = 0; b < 4; b++) {
            xv[b] = x4[b * 10240 + c];
            xv2[b] = x4[b * 10240 + c2];
        }
#pragma unroll
        for (int r = 0; r < 8; r++) {
            const float4* __restrict__ wrow = (const float4*)(W + (size_t)(row0 + r) * 40960);
            const float4 w = __ldcs(wrow + c);
            const float4 w2 = __ldcs(wrow + c2);
#pragma unroll
            for (int b = 0; b < 4; b++) {
                acc[r][b] += w.x * xv[b].x + w.y * xv[b].y + w.z * xv[b].z + w.w * xv[b].w;
                acc[r][b] += w2.x * xv2[b].x + w2.y * xv2[b].y + w2.z * xv2[b].z + w2.w * xv2[b].w;
            }
        }
    }

#pragma unroll
    for (int r = 0; r < 8; r++)
#pragma unroll
        for (int b = 0; b < 4; b++)
#pragma unroll
            for (int off = 16; off; off >>= 1)
                acc[r][b] += __shfl_down_sync(0xffffffffu, acc[r][b], off);

    __shared__ float sred[8][8][4];
    const int lane = tid & 31, wid = tid >> 5;
    if (lane == 0) {
#pragma unroll
        for (int r = 0; r < 8; r++)
#pragma unroll
            for (int b = 0; b < 4; b++) sred[wid][r][b] = acc[r][b];
    }
    __syncthreads();

    if (tid < 32) {
        const int r = tid >> 2, b = tid & 3;
        float s = 0.f;
#pragma unroll
        for (int w = 0; w < 8; w++) s += sred[w][r][b];
        s += bias[row0 + r];
        s = (s >= 0.f) ? s : 0.4f * s;
        g_hfc[b * 4096 + row0 + r] = s;
    }
}

// ---------------- Kernel 2: conv chain + instance norm ----------------
template <int CIN, int HIN, int WIN, int COUT, int HOUT, int WOUT, int STRIDE>
__device__ __forceinline__ void conv_in(const float* __restrict__ in, float* __restrict__ out,
                                        const float* __restrict__ wgt,
                                        const float* __restrict__ bias,
                                        float* smean, float* srstd, int tid) {
    const int S = HOUT * WOUT;
    for (int idx = tid; idx < COUT * S; idx += 256) {
        const int c = idx / S;
        const int rem = idx - c * S;
        const int y = rem / WOUT;
        const int xx = rem - y * WOUT;
        float acc = bias[c];
        for (int ic = 0; ic < CIN; ic++) {
            const float* __restrict__ ip = in + ic * HIN * WIN;
            const float* __restrict__ wp = wgt + (c * CIN + ic) * 9;
#pragma unroll
            for (int dy = 0; dy < 3; dy++) {
                const int yy = y * STRIDE + dy - 1;
                if (yy < 0 || yy >= HIN) continue;
#pragma unroll
                for (int dx = 0; dx < 3; dx++) {
                    const int xs = xx * STRIDE + dx - 1;
                    if (xs < 0 || xs >= WIN) continue;
                    acc += ip[yy * WIN + xs] * wp[dy * 3 + dx];
                }
            }
        }
        out[idx] = acc;
    }
    __syncthreads();

    const int wid = tid >> 5, lane = tid & 31;
    for (int c = wid; c < COUT; c += 8) {
        float s = 0.f, s2 = 0.f;
        for (int e = lane; e < S; e += 32) {
            const float v = out[c * S + e];
            s += v;
            s2 += v * v;
        }
#pragma unroll
        for (int off = 16; off; off >>= 1) {
            s += __shfl_down_sync(0xffffffffu, s, off);
            s2 += __shfl_down_sync(0xffffffffu, s2, off);
        }
        if (lane == 0) {
            const float m = s / (float)S;
            const float var = s2 / (float)S - m * m;
            smean[c] = m;
            srstd[c] = rsqrtf(var + 1e-5f);
        }
    }
    __syncthreads();
    for (int idx = tid; idx < COUT * S; idx += 256) {
        const int c = idx / S;
        out[idx] = (out[idx] - smean[c]) * srstd[c];
    }
    __syncthreads();
}

__global__ __launch_bounds__(256) void conv_chain_kernel(
    const float* __restrict__ w0, const float* __restrict__ b0,
    const float* __restrict__ w1, const float* __restrict__ b1,
    const float* __restrict__ w2, const float* __restrict__ b2,
    const float* __restrict__ w3, const float* __restrict__ b3,
    const float* __restrict__ w4, const float* __restrict__ b4,
    const float* __restrict__ w5, const float* __restrict__ b5) {
    __shared__ float bufA[4096];
    __shared__ float bufB[4096];
    __shared__ float smean[64];
    __shared__ float srstd[64];
    const int n = blockIdx.x;
    const int tid = threadIdx.x;

    for (int i = tid; i < 4096; i += 256) bufA[i] = g_hfc[n * 4096 + i];
    __syncthreads();

    conv_in<1, 4, 1024, 1, 4, 1024, 1>(bufA, bufB, w0, b0, smean, srstd, tid);
    conv_in<1, 4, 1024, 4, 2, 512, 2>(bufB, bufA, w1, b1, smean, srstd, tid);
    conv_in<4, 2, 512, 8, 1, 256, 2>(bufA, bufB, w2, b2, smean, srstd, tid);
    conv_in<8, 1, 256, 16, 1, 128, 2>(bufB, bufA, w3, b3, smean, srstd, tid);
    conv_in<16, 1, 128, 32, 1, 64, 2>(bufA, bufB, w4, b4, smean, srstd, tid);
    conv_in<32, 1, 64, 64, 1, 32, 2>(bufB, bufA, w5, b5, smean, srstd, tid);

    for (int i = tid; i < 2048; i += 256) g_seq[n * 2048 + i] = bufA[i];
}

// ---------------- Kernel 3: layer-0 input projection + flag reset ----------------
// grid = 64 blocks: bid = t*32 + b*8 + jg; warp w computes j = jg*8 + w.
__global__ __launch_bounds__(256) void rnn_pre_kernel(const float* __restrict__ W_ih0,
                                                      const float* __restrict__ b_ih0) {
    const int bid = blockIdx.x;
    const int t = bid >> 5;
    const int b = (bid >> 3) & 3;
    const int jg = bid & 7;
    const int tid = threadIdx.x;
    const int w = tid >> 5, lane = tid & 31;
    const int j = jg * 8 + w;

    if (bid == 0 && tid < 128) g_flag[tid] = 0;  // reset pipeline flags

    const float4* __restrict__ xr = (const float4*)(g_seq + t * 4096 + b * 1024);
    const float4* __restrict__ wr = (const float4*)(W_ih0 + j * 1024);
    float a = 0.f;
#pragma unroll
    for (int i = 0; i < 8; i++) {
        const float4 wv = wr[i * 32 + lane];
        const float4 xv = xr[i * 32 + lane];
        a += wv.x * xv.x + wv.y * xv.y + wv.z * xv.z + wv.w * xv.w;
    }
#pragma unroll
    for (int off = 16; off; off >>= 1) a += __shfl_down_sync(0xffffffffu, a, off);
    if (lane == 0) g_pre[t * 256 + b * 64 + j] = a + b_ih0[j];
}

// ---------------- Kernel 4: pipelined 64-layer RNN + output head ----------------
__device__ __forceinline__ void flag_release(int idx) {
    int* p = (int*)&g_flag[idx];
    asm volatile("st.release.gpu.u32 [%0], %1;" ::"l"(p), "r"(1) : "memory");
}
__device__ __forceinline__ void flag_wait(int idx) {
    int* p = (int*)&g_flag[idx];
    int v;
    do {
        asm volatile("ld.acquire.gpu.u32 %0, [%1];" : "=r"(v) : "l"(p) : "memory");
    } while (v == 0);
}

__global__ __launch_bounds__(256) void rnn_pipe_kernel(
    const float* __restrict__ W_ihr, const float* __restrict__ b_ihr,
    const float* __restrict__ W_hh, const float* __restrict__ b_hh,
    const float* __restrict__ W_out, const float* __restrict__ b_out,
    float* __restrict__ out) {
    const int l = blockIdx.x;     // layer
    const int tid = threadIdx.x;
    const int j = tid >> 2;       // output row 0..63
    const int s = tid & 3;        // k-segment 0..3 (16 elems)

    __shared__ float sh[2][4][64];   // h[t][b][j]
    __shared__ float yin[4][64];     // incoming layer output

    // preload weights into registers
    float4 wi4[4], wh4[4];
    if (l >= 1) {
        const float4* __restrict__ Wi = (const float4*)(W_ihr + (size_t)(l - 1) * 4096 + j * 64 + s * 16);
#pragma unroll
        for (int i = 0; i < 4; i++) wi4[i] = Wi[i];
    }
    const float4* __restrict__ Wh = (const float4*)(W_hh + (size_t)l * 4096 + j * 64 + s * 16);
#pragma unroll
    for (int i = 0; i < 4; i++) wh4[i] = Wh[i];

    // per-(j) combined bias, read by s==0 threads only
    float cb = 0.f;
    if (s == 0) {
        cb = b_hh[l * 64 + j];
        if (l >= 1) cb += b_ihr[(l - 1) * 64 + j];
    }

#pragma unroll
    for (int t = 0; t < 2; t++) {
        float p[4] = {0.f, 0.f, 0.f, 0.f};

        if (l >= 1) {
            if (tid == 0) flag_wait((l - 1) * 2 + t);
            __syncthreads();
            if (tid < 64) ((float4*)&yin[0][0])[tid] = ((const float4*)(g_y + ((size_t)(l - 1) * 2 + t) * 256))[tid];
            __syncthreads();
            // input projection partial
#pragma unroll
            for (int i = 0; i < 4; i++) {
                const float4 w = wi4[i];
#pragma unroll
                for (int b = 0; b < 4; b++) {
                    p[b] += w.x * yin[b][s * 16 + 4 * i + 0];
                    p[b] += w.y * yin[b][s * 16 + 4 * i + 1];
                    p[b] += w.z * yin[b][s * 16 + 4 * i + 2];
                    p[b] += w.w * yin[b][s * 16 + 4 * i + 3];
                }
            }
        }
        if (t == 1) {
            // recurrent partial from sh[0]
#pragma unroll
            for (int i = 0; i < 4; i++) {
                const float4 w = wh4[i];
#pragma unroll
                for (int b = 0; b < 4; b++) {
                    p[b] += w.x * sh[0][b][s * 16 + 4 * i + 0];
                    p[b] += w.y * sh[0][b][s * 16 + 4 * i + 1];
                    p[b] += w.z * sh[0][b][s * 16 + 4 * i + 2];
                    p[b] += w.w * sh[0][b][s * 16 + 4 * i + 3];
                }
            }
        }
        // reduce over 4-lane groups
#pragma unroll
        for (int b = 0; b < 4; b++) {
            p[b] += __shfl_down_sync(0xffffffffu, p[b], 2, 4);
            p[b] += __shfl_down_sync(0xffffffffu, p[b], 1, 4);
        }

        if (s == 0) {
            float* yo = g_y + ((size_t)l * 2 + t) * 256;
#pragma unroll
            for (int b = 0; b < 4; b++) {
                float a = p[b] + cb;
                if (l == 0) a += g_pre[t * 256 + b * 64 + j];
                const float h = tanhf(a);
                sh[t][b][j] = h;
                yo[b * 64 + j] = h;
            }
            __threadfence();
        }
        __syncthreads();
        if (tid == 0) flag_release(l * 2 + t);
    }

    // ---- output head: only layer 63's block ----
    if (l == 63) {
        for (int idx = tid; idx < 272; idx += 256) {
            const int t = idx / 136;
            const int rem = idx - t * 136;
            const int bb = rem / 34;
            const int o = rem - bb * 34;
            float a = b_out[o];
            const float4* __restrict__ Wo4 = (const float4*)(W_out + o * 64);
#pragma unroll
            for (int i4 = 0; i4 < 16; i4++) {
                const float4 w = Wo4[i4];
                a += w.x * sh[t][bb][4 * i4 + 0] + w.y * sh[t][bb][4 * i4 + 1] +
                     w.z * sh[t][bb][4 * i4 + 2] + w.w * sh[t][bb][4 * i4 + 3];
            }
            out[idx] = (a >= 0.f) ? a : 0.4f * a;
        }
    }
}

// ---------------- launch ----------------
extern "C" void kernel_launch(void* const* d_in, const int* in_sizes, int n_in,
                              void* d_out, int out_size) {
    const float* x     = (const float*)d_in[0];
    const float* W_fc  = (const float*)d_in[1];
    const float* b_fc  = (const float*)d_in[2];
    const float* w0    = (const float*)d_in[3];
    const float* b0    = (const float*)d_in[4];
    const float* w1    = (const float*)d_in[5];
    const float* b1    = (const float*)d_in[6];
    const float* w2    = (const float*)d_in[7];
    const float* b2    = (const float*)d_in[8];
    const float* w3    = (const float*)d_in[9];
    const float* b3    = (const float*)d_in[10];
    const float* w4    = (const float*)d_in[11];
    const float* b4    = (const float*)d_in[12];
    const float* w5    = (const float*)d_in[13];
    const float* b5    = (const float*)d_in[14];
    const float* W_ih0 = (const float*)d_in[15];
    const float* b_ih0 = (const float*)d_in[16];
    const float* W_ihr = (const float*)d_in[17];
    const float* b_ihr = (const float*)d_in[18];
    const float* W_hh  = (const float*)d_in[19];
    const float* b_hh  = (const float*)d_in[20];
    const float* W_out = (const float*)d_in[21];
    const float* b_out = (const float*)d_in[22];
    float* out = (float*)d_out;

    fc_kernel<<<512, 256>>>(x, W_fc, b_fc);
    conv_chain_kernel<<<4, 256>>>(w0, b0, w1, b1, w2, b2, w3, b3, w4, b4, w5, b5);
    rnn_pre_kernel<<<64, 256>>>(W_ih0, b_ih0);
    rnn_pipe_kernel<<<64, 256>>>(W_ihr, b_ihr, W_hh, b_hh, W_out, b_out, out);
}

// round 4
// speedup vs baseline: 3.3312x; 1.0720x over previous
#include <cuda_runtime.h>
#include <math.h>

#define NB   11          // RNN pipeline blocks
#define LPB  6           // layers per block (last block gets 4)
#define NBND (NB - 1)    // boundaries

// ---------------- scratch (no allocations allowed) ----------------
__device__ float g_hfc[4 * 4096];          // FC output, (4, 4096)
__device__ float g_seq[2 * 4096];          // conv-chain output (T=2,B=4,1024)
__device__ float g_pre[2 * 4 * 64];        // layer-0 input projection (+b_ih0)
__device__ float g_bnd[NBND * 2 * 4 * 64]; // boundary layer outputs
__device__ int   g_flagJ[NBND * 2 * 64];   // per-(boundary,t,j) flags

// ---------------- packed f32x2 helpers (sm_103a) ----------------
__device__ __forceinline__ unsigned long long ffma2(unsigned long long a,
                                                    unsigned long long b,
                                                    unsigned long long c) {
    unsigned long long d;
    asm("fma.rn.f32x2 %0, %1, %2, %3;" : "=l"(d) : "l"(a), "l"(b), "l"(c));
    return d;
}
__device__ __forceinline__ float upk_sum(unsigned long long v) {
    float lo, hi;
    asm("mov.b64 {%0,%1}, %2;" : "=f"(lo), "=f"(hi) : "l"(v));
    return lo + hi;
}

// ---------------- Kernel 1: FC  h = leaky(x @ W^T + b) ----------------
__global__ __launch_bounds__(256) void fc_kernel(const float* __restrict__ x,
                                                 const float* __restrict__ W,
                                                 const float* __restrict__ bias) {
    const int row0 = blockIdx.x * 8;
    const int tid = threadIdx.x;

    float acc[8][4];
#pragma unroll
    for (int r = 0; r < 8; r++)
#pragma unroll
        for (int b = 0; b < 4; b++) acc[r][b] = 0.f;

    const float4* __restrict__ x4 = (const float4*)x;

    for (int c = tid; c < 10240; c += 512) {
        const int c2 = c + 256;
        float4 xv[4], xv2[4];
#pragma unroll
        for (int b = 0; b < 4; b++) {
            xv[b] = x4[b * 10240 + c];
            xv2[b] = x4[b * 10240 + c2];
        }
#pragma unroll
        for (int r = 0; r < 8; r++) {
            const float4* __restrict__ wrow = (const float4*)(W + (size_t)(row0 + r) * 40960);
            const float4 w = __ldcs(wrow + c);
            const float4 w2 = __ldcs(wrow + c2);
#pragma unroll
            for (int b = 0; b < 4; b++) {
                acc[r][b] += w.x * xv[b].x + w.y * xv[b].y + w.z * xv[b].z + w.w * xv[b].w;
                acc[r][b] += w2.x * xv2[b].x + w2.y * xv2[b].y + w2.z * xv2[b].z + w2.w * xv2[b].w;
            }
        }
    }

#pragma unroll
    for (int r = 0; r < 8; r++)
#pragma unroll
        for (int b = 0; b < 4; b++)
#pragma unroll
            for (int off = 16; off; off >>= 1)
                acc[r][b] += __shfl_down_sync(0xffffffffu, acc[r][b], off);

    __shared__ float sred[8][8][4];
    const int lane = tid & 31, wid = tid >> 5;
    if (lane == 0) {
#pragma unroll
        for (int r = 0; r < 8; r++)
#pragma unroll
            for (int b = 0; b < 4; b++) sred[wid][r][b] = acc[r][b];
    }
    __syncthreads();

    if (tid < 32) {
        const int r = tid >> 2, b = tid & 3;
        float s = 0.f;
#pragma unroll
        for (int w = 0; w < 8; w++) s += sred[w][r][b];
        s += bias[row0 + r];
        s = (s >= 0.f) ? s : 0.4f * s;
        g_hfc[b * 4096 + row0 + r] = s;
    }
}

// ---------------- Kernel 2: conv chain + instance norm ----------------
template <int CIN, int HIN, int WIN, int COUT, int HOUT, int WOUT, int STRIDE>
__device__ __forceinline__ void conv_in(const float* __restrict__ in, float* __restrict__ out,
                                        const float* __restrict__ wgt,
                                        const float* __restrict__ bias,
                                        float* smean, float* srstd, int tid) {
    const int S = HOUT * WOUT;
    for (int idx = tid; idx < COUT * S; idx += 256) {
        const int c = idx / S;
        const int rem = idx - c * S;
        const int y = rem / WOUT;
        const int xx = rem - y * WOUT;
        float acc = bias[c];
        for (int ic = 0; ic < CIN; ic++) {
            const float* __restrict__ ip = in + ic * HIN * WIN;
            const float* __restrict__ wp = wgt + (c * CIN + ic) * 9;
#pragma unroll
            for (int dy = 0; dy < 3; dy++) {
                const int yy = y * STRIDE + dy - 1;
                if (yy < 0 || yy >= HIN) continue;
#pragma unroll
                for (int dx = 0; dx < 3; dx++) {
                    const int xs = xx * STRIDE + dx - 1;
                    if (xs < 0 || xs >= WIN) continue;
                    acc += ip[yy * WIN + xs] * wp[dy * 3 + dx];
                }
            }
        }
        out[idx] = acc;
    }
    __syncthreads();

    const int wid = tid >> 5, lane = tid & 31;
    for (int c = wid; c < COUT; c += 8) {
        float s = 0.f, s2 = 0.f;
        for (int e = lane; e < S; e += 32) {
            const float v = out[c * S + e];
            s += v;
            s2 += v * v;
        }
#pragma unroll
        for (int off = 16; off; off >>= 1) {
            s += __shfl_down_sync(0xffffffffu, s, off);
            s2 += __shfl_down_sync(0xffffffffu, s2, off);
        }
        if (lane == 0) {
            const float m = s / (float)S;
            const float var = s2 / (float)S - m * m;
            smean[c] = m;
            srstd[c] = rsqrtf(var + 1e-5f);
        }
    }
    __syncthreads();
    for (int idx = tid; idx < COUT * S; idx += 256) {
        const int c = idx / S;
        out[idx] = (out[idx] - smean[c]) * srstd[c];
    }
    __syncthreads();
}

__global__ __launch_bounds__(256) void conv_chain_kernel(
    const float* __restrict__ w0, const float* __restrict__ b0,
    const float* __restrict__ w1, const float* __restrict__ b1,
    const float* __restrict__ w2, const float* __restrict__ b2,
    const float* __restrict__ w3, const float* __restrict__ b3,
    const float* __restrict__ w4, const float* __restrict__ b4,
    const float* __restrict__ w5, const float* __restrict__ b5) {
    __shared__ float bufA[4096];
    __shared__ float bufB[4096];
    __shared__ float smean[64];
    __shared__ float srstd[64];
    const int n = blockIdx.x;
    const int tid = threadIdx.x;

    for (int i = tid; i < 4096; i += 256) bufA[i] = g_hfc[n * 4096 + i];
    __syncthreads();

    conv_in<1, 4, 1024, 1, 4, 1024, 1>(bufA, bufB, w0, b0, smean, srstd, tid);
    conv_in<1, 4, 1024, 4, 2, 512, 2>(bufB, bufA, w1, b1, smean, srstd, tid);
    conv_in<4, 2, 512, 8, 1, 256, 2>(bufA, bufB, w2, b2, smean, srstd, tid);
    conv_in<8, 1, 256, 16, 1, 128, 2>(bufB, bufA, w3, b3, smean, srstd, tid);
    conv_in<16, 1, 128, 32, 1, 64, 2>(bufA, bufB, w4, b4, smean, srstd, tid);
    conv_in<32, 1, 64, 64, 1, 32, 2>(bufB, bufA, w5, b5, smean, srstd, tid);

    for (int i = tid; i < 2048; i += 256) g_seq[n * 2048 + i] = bufA[i];
}

// ---------------- Kernel 3: layer-0 input projection + flag reset ----------------
__global__ __launch_bounds__(256) void rnn_pre_kernel(const float* __restrict__ W_ih0,
                                                      const float* __restrict__ b_ih0) {
    const int bid = blockIdx.x;
    const int t = bid >> 5;
    const int b = (bid >> 3) & 3;
    const int jg = bid & 7;
    const int tid = threadIdx.x;
    const int w = tid >> 5, lane = tid & 31;
    const int j = jg * 8 + w;

    if (bid == 0) {  // reset pipeline flags for this replay
        for (int i = tid; i < NBND * 2 * 64; i += 256) g_flagJ[i] = 0;
    }

    const float4* __restrict__ xr = (const float4*)(g_seq + t * 4096 + b * 1024);
    const float4* __restrict__ wr = (const float4*)(W_ih0 + j * 1024);
    float a = 0.f;
#pragma unroll
    for (int i = 0; i < 8; i++) {
        const float4 wv = wr[i * 32 + lane];
        const float4 xv = xr[i * 32 + lane];
        a += wv.x * xv.x + wv.y * xv.y + wv.z * xv.z + wv.w * xv.w;
    }
#pragma unroll
    for (int off = 16; off; off >>= 1) a += __shfl_down_sync(0xffffffffu, a, off);
    if (lane == 0) g_pre[t * 256 + b * 64 + j] = a + b_ih0[j];
}

// ---------------- Kernel 4: multi-layer-per-block pipelined RNN ----------------
// smem layout (floats): swi[6][4096] | swh[6][4096] | sb[6][64] | yy[4][64] |
//                       h0[6][4][64] | spre[2][256]
#define SMEM_FLOATS (2 * LPB * 4096 + LPB * 64 + 256 + LPB * 256 + 512)

__global__ __launch_bounds__(256) void rnn_pipe2_kernel(
    const float* __restrict__ W_ihr, const float* __restrict__ b_ihr,
    const float* __restrict__ W_hh, const float* __restrict__ b_hh,
    const float* __restrict__ W_out, const float* __restrict__ b_out,
    float* __restrict__ out) {
    extern __shared__ float sm[];
    const int bid = blockIdx.x;
    const int l0 = bid * LPB;
    const int nl = (bid == NB - 1) ? (64 - l0) : LPB;
    const int tid = threadIdx.x;
    const int j = tid >> 2, s = tid & 3;

    float* swi = sm;
    float* swh = swi + LPB * 4096;
    float* sb  = swh + LPB * 4096;
    float* yy  = sb + LPB * 64;
    float* h0  = yy + 256;
    float* spre = h0 + LPB * 256;

    // ---- preload weights + biases into smem (all blocks in parallel) ----
    for (int ll = 0; ll < nl; ll++) {
        const int l = l0 + ll;
        float4* dsth = (float4*)(swh + ll * 4096);
        const float4* srch = (const float4*)(W_hh + (size_t)l * 4096);
        for (int i = tid; i < 1024; i += 256) dsth[i] = srch[i];
        if (l >= 1) {
            float4* dsti = (float4*)(swi + ll * 4096);
            const float4* srci = (const float4*)(W_ihr + (size_t)(l - 1) * 4096);
            for (int i = tid; i < 1024; i += 256) dsti[i] = srci[i];
        }
        if (tid < 64)
            sb[ll * 64 + tid] = b_hh[l * 64 + tid] + (l >= 1 ? b_ihr[(l - 1) * 64 + tid] : 0.f);
    }
    if (bid == 0) {
        for (int i = tid; i < 512; i += 256) spre[i] = g_pre[i];
    }
    __syncthreads();

    for (int t = 0; t < 2; t++) {
        // ---- acquire boundary input y(t) from upstream block ----
        if (bid > 0) {
            if (tid < 64) {
                int* fp = g_flagJ + ((bid - 1) * 2 + t) * 64 + tid;
                int v;
                do {
                    asm volatile("ld.acquire.gpu.u32 %0, [%1];" : "=r"(v) : "l"(fp) : "memory");
                } while (!v);
                const float* src = g_bnd + ((bid - 1) * 2 + t) * 256;
#pragma unroll
                for (int b = 0; b < 4; b++) yy[b * 64 + tid] = src[b * 64 + tid];
            }
        }
        __syncthreads();

        for (int ll = 0; ll < nl; ll++) {
            const bool first = (bid == 0 && ll == 0);
            unsigned long long acc[4] = {0ull, 0ull, 0ull, 0ull};

            if (!first) {
                const unsigned long long* w2 =
                    (const unsigned long long*)(swi + ll * 4096 + j * 64 + s * 16);
#pragma unroll
                for (int i = 0; i < 8; i++) {
                    const unsigned long long w = w2[i];
#pragma unroll
                    for (int b = 0; b < 4; b++) {
                        const unsigned long long yv =
                            ((const unsigned long long*)(yy + b * 64 + s * 16))[i];
                        acc[b] = ffma2(w, yv, acc[b]);
                    }
                }
            }
            if (t == 1) {
                const unsigned long long* w2 =
                    (const unsigned long long*)(swh + ll * 4096 + j * 64 + s * 16);
                const float* hp = h0 + ll * 256;
#pragma unroll
                for (int i = 0; i < 8; i++) {
                    const unsigned long long w = w2[i];
#pragma unroll
                    for (int b = 0; b < 4; b++) {
                        const unsigned long long hv =
                            ((const unsigned long long*)(hp + b * 64 + s * 16))[i];
                        acc[b] = ffma2(w, hv, acc[b]);
                    }
                }
            }

            float p[4];
#pragma unroll
            for (int b = 0; b < 4; b++) {
                p[b] = upk_sum(acc[b]);
                p[b] += __shfl_down_sync(0xffffffffu, p[b], 2, 4);
                p[b] += __shfl_down_sync(0xffffffffu, p[b], 1, 4);
            }

            __syncthreads();  // all reads of yy done before overwrite
            if (s == 0) {
                const float cb = sb[ll * 64 + j];
                const bool last_bnd = (ll == nl - 1) && (bid < NB - 1);
#pragma unroll
                for (int b = 0; b < 4; b++) {
                    float a = p[b] + cb;
                    if (first) a += spre[t * 256 + b * 64 + j];
                    const float h = tanhf(a);
                    if (t == 0) h0[ll * 256 + b * 64 + j] = h;
                    yy[b * 64 + j] = h;
                    if (last_bnd) g_bnd[(bid * 2 + t) * 256 + b * 64 + j] = h;
                }
                if (last_bnd) {
                    int* fp = g_flagJ + (bid * 2 + t) * 64 + j;
                    asm volatile("st.release.gpu.u32 [%0], %1;" ::"l"(fp), "r"(1) : "memory");
                }
            }
            __syncthreads();
        }
    }

    // ---- output head: last block only. h(t=0) in h0[nl-1], h(t=1) in yy ----
    if (bid == NB - 1) {
        const float* hT0 = h0 + (nl - 1) * 256;
        for (int idx = tid; idx < 272; idx += 256) {
            const int t = idx / 136;
            const int rem = idx - t * 136;
            const int bb = rem / 34;
            const int o = rem - bb * 34;
            const float* src = (t == 0) ? (hT0 + bb * 64) : (yy + bb * 64);
            float a = b_out[o];
            const float4* __restrict__ Wo4 = (const float4*)(W_out + o * 64);
#pragma unroll
            for (int i4 = 0; i4 < 16; i4++) {
                const float4 w = Wo4[i4];
                const float4 v = ((const float4*)src)[i4];
                a += w.x * v.x + w.y * v.y + w.z * v.z + w.w * v.w;
            }
            out[idx] = (a >= 0.f) ? a : 0.4f * a;
        }
    }
}

// ---------------- launch ----------------
extern "C" void kernel_launch(void* const* d_in, const int* in_sizes, int n_in,
                              void* d_out, int out_size) {
    const float* x     = (const float*)d_in[0];
    const float* W_fc  = (const float*)d_in[1];
    const float* b_fc  = (const float*)d_in[2];
    const float* w0    = (const float*)d_in[3];
    const float* b0    = (const float*)d_in[4];
    const float* w1    = (const float*)d_in[5];
    const float* b1    = (const float*)d_in[6];
    const float* w2    = (const float*)d_in[7];
    const float* b2    = (const float*)d_in[8];
    const float* w3    = (const float*)d_in[9];
    const float* b3    = (const float*)d_in[10];
    const float* w4    = (const float*)d_in[11];
    const float* b4    = (const float*)d_in[12];
    const float* w5    = (const float*)d_in[13];
    const float* b5    = (const float*)d_in[14];
    const float* W_ih0 = (const float*)d_in[15];
    const float* b_ih0 = (const float*)d_in[16];
    const float* W_ihr = (const float*)d_in[17];
    const float* b_ihr = (const float*)d_in[18];
    const float* W_hh  = (const float*)d_in[19];
    const float* b_hh  = (const float*)d_in[20];
    const float* W_out = (const float*)d_in[21];
    const float* b_out = (const float*)d_in[22];
    float* out = (float*)d_out;

    const size_t smem_bytes = SMEM_FLOATS * sizeof(float);

    // Set the opt-in smem limit only outside capture (first correctness call
    // sets it; the attribute persists for the captured launches).
    cudaStreamCaptureStatus cap = cudaStreamCaptureStatusNone;
    cudaStreamIsCapturing(cudaStreamLegacy, &cap);
    if (cap == cudaStreamCaptureStatusNone) {
        cudaFuncSetAttribute(rnn_pipe2_kernel,
                             cudaFuncAttributeMaxDynamicSharedMemorySize,
                             (int)smem_bytes);
    }

    fc_kernel<<<512, 256>>>(x, W_fc, b_fc);
    conv_chain_kernel<<<4, 256>>>(w0, b0, w1, b1, w2, b2, w3, b3, w4, b4, w5, b5);
    rnn_pre_kernel<<<64, 256>>>(W_ih0, b_ih0);
    rnn_pipe2_kernel<<<NB, 256, smem_bytes>>>(W_ihr, b_ihr, W_hh, b_hh, W_out, b_out, out);
}

// round 6
// speedup vs baseline: 3.3716x; 1.0121x over previous
#include <cuda_runtime.h>
#include <math.h>

#define NB   32          // RNN pipeline blocks
#define LPB  2           // layers per block
#define NBND (NB - 1)    // boundaries

// ---------------- scratch (no allocations allowed) ----------------
__device__ float g_hfc[4 * 4096];                     // FC output, (4, 4096)
__device__ float g_seq[2 * 4096];                     // conv-chain output (T=2,B=4,1024)
__device__ float g_pre[2 * 4 * 64];                   // layer-0 input projection (+b_ih0)
__device__ unsigned long long g_bnd2[NBND * 2 * 256]; // packed {h_bits, valid} per (bnd,t,b,j)

typedef unsigned long long ull;

// ---------------- packed f32x2 helpers (sm_103a) ----------------
__device__ __forceinline__ ull ffma2(ull a, ull b, ull c) {
    ull d;
    asm("fma.rn.f32x2 %0, %1, %2, %3;" : "=l"(d) : "l"(a), "l"(b), "l"(c));
    return d;
}
__device__ __forceinline__ float upk_sum(ull v) {
    float lo, hi;
    asm("mov.b64 {%0,%1}, %2;" : "=f"(lo), "=f"(hi) : "l"(v));
    return lo + hi;
}

// ---------------- Kernel 1: FC  h = leaky(x @ W^T + b) ----------------
__global__ __launch_bounds__(256) void fc_kernel(const float* __restrict__ x,
                                                 const float* __restrict__ W,
                                                 const float* __restrict__ bias) {
    const int row0 = blockIdx.x * 8;
    const int tid = threadIdx.x;

    float acc[8][4];
#pragma unroll
    for (int r = 0; r < 8; r++)
#pragma unroll
        for (int b = 0; b < 4; b++) acc[r][b] = 0.f;

    const float4* __restrict__ x4 = (const float4*)x;

    for (int c = tid; c < 10240; c += 512) {
        const int c2 = c + 256;
        float4 xv[4], xv2[4];
#pragma unroll
        for (int b = 0; b < 4; b++) {
            xv[b] = x4[b * 10240 + c];
            xv2[b] = x4[b * 10240 + c2];
        }
#pragma unroll
        for (int r = 0; r < 8; r++) {
            const float4* __restrict__ wrow = (const float4*)(W + (size_t)(row0 + r) * 40960);
            const float4 w = __ldcs(wrow + c);
            const float4 w2 = __ldcs(wrow + c2);
#pragma unroll
            for (int b = 0; b < 4; b++) {
                acc[r][b] += w.x * xv[b].x + w.y * xv[b].y + w.z * xv[b].z + w.w * xv[b].w;
                acc[r][b] += w2.x * xv2[b].x + w2.y * xv2[b].y + w2.z * xv2[b].z + w2.w * xv2[b].w;
            }
        }
    }

#pragma unroll
    for (int r = 0; r < 8; r++)
#pragma unroll
        for (int b = 0; b < 4; b++)
#pragma unroll
            for (int off = 16; off; off >>= 1)
                acc[r][b] += __shfl_down_sync(0xffffffffu, acc[r][b], off);

    __shared__ float sred[8][8][4];
    const int lane = tid & 31, wid = tid >> 5;
    if (lane == 0) {
#pragma unroll
        for (int r = 0; r < 8; r++)
#pragma unroll
            for (int b = 0; b < 4; b++) sred[wid][r][b] = acc[r][b];
    }
    __syncthreads();

    if (tid < 32) {
        const int r = tid >> 2, b = tid & 3;
        float s = 0.f;
#pragma unroll
        for (int w = 0; w < 8; w++) s += sred[w][r][b];
        s += bias[row0 + r];
        s = (s >= 0.f) ? s : 0.4f * s;
        g_hfc[b * 4096 + row0 + r] = s;
    }
}

// ---------------- Kernel 2: conv chain + instance norm ----------------
template <int CIN, int HIN, int WIN, int COUT, int HOUT, int WOUT, int STRIDE>
__device__ __forceinline__ void conv_in(const float* __restrict__ in, float* __restrict__ out,
                                        const float* __restrict__ wgt,
                                        const float* __restrict__ bias,
                                        float* smean, float* srstd, int tid) {
    const int S = HOUT * WOUT;
    for (int idx = tid; idx < COUT * S; idx += 256) {
        const int c = idx / S;
        const int rem = idx - c * S;
        const int y = rem / WOUT;
        const int xx = rem - y * WOUT;
        float acc = bias[c];
        for (int ic = 0; ic < CIN; ic++) {
            const float* __restrict__ ip = in + ic * HIN * WIN;
            const float* __restrict__ wp = wgt + (c * CIN + ic) * 9;
#pragma unroll
            for (int dy = 0; dy < 3; dy++) {
                const int yy = y * STRIDE + dy - 1;
                if (yy < 0 || yy >= HIN) continue;
#pragma unroll
                for (int dx = 0; dx < 3; dx++) {
                    const int xs = xx * STRIDE + dx - 1;
                    if (xs < 0 || xs >= WIN) continue;
                    acc += ip[yy * WIN + xs] * wp[dy * 3 + dx];
                }
            }
        }
        out[idx] = acc;
    }
    __syncthreads();

    const int wid = tid >> 5, lane = tid & 31;
    for (int c = wid; c < COUT; c += 8) {
        float s = 0.f, s2 = 0.f;
        for (int e = lane; e < S; e += 32) {
            const float v = out[c * S + e];
            s += v;
            s2 += v * v;
        }
#pragma unroll
        for (int off = 16; off; off >>= 1) {
            s += __shfl_down_sync(0xffffffffu, s, off);
            s2 += __shfl_down_sync(0xffffffffu, s2, off);
        }
        if (lane == 0) {
            const float m = s / (float)S;
            const float var = s2 / (float)S - m * m;
            smean[c] = m;
            srstd[c] = rsqrtf(var + 1e-5f);
        }
    }
    __syncthreads();
    for (int idx = tid; idx < COUT * S; idx += 256) {
        const int c = idx / S;
        out[idx] = (out[idx] - smean[c]) * srstd[c];
    }
    __syncthreads();
}

__global__ __launch_bounds__(256) void conv_chain_kernel(
    const float* __restrict__ w0, const float* __restrict__ b0,
    const float* __restrict__ w1, const float* __restrict__ b1,
    const float* __restrict__ w2, const float* __restrict__ b2,
    const float* __restrict__ w3, const float* __restrict__ b3,
    const float* __restrict__ w4, const float* __restrict__ b4,
    const float* __restrict__ w5, const float* __restrict__ b5) {
    __shared__ float bufA[4096];
    __shared__ float bufB[4096];
    __shared__ float smean[64];
    __shared__ float srstd[64];
    const int n = blockIdx.x;
    const int tid = threadIdx.x;

    for (int i = tid; i < 4096; i += 256) bufA[i] = g_hfc[n * 4096 + i];
    __syncthreads();

    conv_in<1, 4, 1024, 1, 4, 1024, 1>(bufA, bufB, w0, b0, smean, srstd, tid);
    conv_in<1, 4, 1024, 4, 2, 512, 2>(bufB, bufA, w1, b1, smean, srstd, tid);
    conv_in<4, 2, 512, 8, 1, 256, 2>(bufA, bufB, w2, b2, smean, srstd, tid);
    conv_in<8, 1, 256, 16, 1, 128, 2>(bufB, bufA, w3, b3, smean, srstd, tid);
    conv_in<16, 1, 128, 32, 1, 64, 2>(bufA, bufB, w4, b4, smean, srstd, tid);
    conv_in<32, 1, 64, 64, 1, 32, 2>(bufB, bufA, w5, b5, smean, srstd, tid);

    for (int i = tid; i < 2048; i += 256) g_seq[n * 2048 + i] = bufA[i];
}

// ---------------- Kernel 3: layer-0 input projection + boundary reset ----------------
__global__ __launch_bounds__(256) void rnn_pre_kernel(const float* __restrict__ W_ih0,
                                                      const float* __restrict__ b_ih0) {
    const int bid = blockIdx.x;
    const int t = bid >> 5;
    const int b = (bid >> 3) & 3;
    const int jg = bid & 7;
    const int tid = threadIdx.x;
    const int w = tid >> 5, lane = tid & 31;
    const int j = jg * 8 + w;

    // reset packed boundary slots for this replay (15872 entries over 16384 threads)
    const int gidx = bid * 256 + tid;
    if (gidx < NBND * 2 * 256) g_bnd2[gidx] = 0ull;

    const float4* __restrict__ xr = (const float4*)(g_seq + t * 4096 + b * 1024);
    const float4* __restrict__ wr = (const float4*)(W_ih0 + j * 1024);
    float a = 0.f;
#pragma unroll
    for (int i = 0; i < 8; i++) {
        const float4 wv = wr[i * 32 + lane];
        const float4 xv = xr[i * 32 + lane];
        a += wv.x * xv.x + wv.y * xv.y + wv.z * xv.z + wv.w * xv.w;
    }
#pragma unroll
    for (int off = 16; off; off >>= 1) a += __shfl_down_sync(0xffffffffu, a, off);
    if (lane == 0) g_pre[t * 256 + b * 64 + j] = a + b_ih0[j];
}

// ---------------- Kernel 4: register-weight pipelined RNN (2 layers/block) ----------------
__global__ __launch_bounds__(256) void rnn_pipe3_kernel(
    const float* __restrict__ W_ihr, const float* __restrict__ b_ihr,
    const float* __restrict__ W_hh, const float* __restrict__ b_hh,
    const float* __restrict__ W_out, const float* __restrict__ b_out,
    float* __restrict__ out) {
    __shared__ float yy[2][256];    // double-buffered layer activations [buf][b*64+j]
    __shared__ float h0s[2][256];   // t=0 hidden per local layer
    __shared__ float sb[2][64];     // combined biases
    __shared__ float spre[512];     // block 0 only: layer-0 input projection

    const int bid = blockIdx.x;
    const int l0 = bid * LPB;
    const int tid = threadIdx.x;
    const int j = tid >> 2;   // output row 0..63
    const int s = tid & 3;    // k-segment 0..3 (16 floats)

    // ---- preload weights into registers (packed f32x2) ----
    ull wi[2][8], wh[2][8];
#pragma unroll
    for (int ll = 0; ll < LPB; ll++) {
        const int l = l0 + ll;
        const ulonglong2* ph = (const ulonglong2*)(W_hh + (size_t)l * 4096 + j * 64 + s * 16);
#pragma unroll
        for (int i = 0; i < 4; i++) {
            const ulonglong2 v = ph[i];
            wh[ll][2 * i] = v.x;
            wh[ll][2 * i + 1] = v.y;
        }
        if (l >= 1) {
            const ulonglong2* pi = (const ulonglong2*)(W_ihr + (size_t)(l - 1) * 4096 + j * 64 + s * 16);
#pragma unroll
            for (int i = 0; i < 4; i++) {
                const ulonglong2 v = pi[i];
                wi[ll][2 * i] = v.x;
                wi[ll][2 * i + 1] = v.y;
            }
        } else {
#pragma unroll
            for (int i = 0; i < 8; i++) wi[ll][i] = 0ull;
        }
    }
    if (tid < 64) {
#pragma unroll
        for (int ll = 0; ll < LPB; ll++) {
            const int l = l0 + ll;
            sb[ll][tid] = b_hh[l * 64 + tid] + (l >= 1 ? b_ihr[(l - 1) * 64 + tid] : 0.f);
        }
    }
    if (bid == 0) {
        for (int i = tid; i < 512; i += 256) spre[i] = g_pre[i];
    }
    __syncthreads();

    for (int t = 0; t < 2; t++) {
        // ---- acquire boundary input y(t): data and flag packed in one u64 ----
        if (bid > 0 && tid < 64) {
            const ull* src = g_bnd2 + ((size_t)(bid - 1) * 2 + t) * 256;
#pragma unroll
            for (int b = 0; b < 4; b++) {
                const ull* p = src + b * 64 + tid;
                ull v;
                do {
                    asm volatile("ld.acquire.gpu.u64 %0, [%1];" : "=l"(v) : "l"(p) : "memory");
                } while ((unsigned)(v >> 32) == 0u);
                yy[0][b * 64 + tid] = __uint_as_float((unsigned)v);
            }
        }
        __syncthreads();

#pragma unroll
        for (int ll = 0; ll < LPB; ll++) {
            const bool first = (bid == 0 && ll == 0);
            const float* yin = yy[ll & 1];
            float* yout = yy[(ll + 1) & 1];

            ull acc[4] = {0ull, 0ull, 0ull, 0ull};
            if (!first) {
#pragma unroll
                for (int b = 0; b < 4; b++) {
                    const ulonglong2* yv = (const ulonglong2*)(yin + b * 64 + s * 16);
#pragma unroll
                    for (int i = 0; i < 4; i++) {
                        const ulonglong2 v = yv[i];
                        acc[b] = ffma2(wi[ll][2 * i], v.x, acc[b]);
                        acc[b] = ffma2(wi[ll][2 * i + 1], v.y, acc[b]);
                    }
                }
            }
            if (t == 1) {
#pragma unroll
                for (int b = 0; b < 4; b++) {
                    const ulonglong2* hv = (const ulonglong2*)(h0s[ll] + b * 64 + s * 16);
#pragma unroll
                    for (int i = 0; i < 4; i++) {
                        const ulonglong2 v = hv[i];
                        acc[b] = ffma2(wh[ll][2 * i], v.x, acc[b]);
                        acc[b] = ffma2(wh[ll][2 * i + 1], v.y, acc[b]);
                    }
                }
            }

            float p4[4];
#pragma unroll
            for (int b = 0; b < 4; b++) {
                p4[b] = upk_sum(acc[b]);
                p4[b] += __shfl_down_sync(0xffffffffu, p4[b], 2, 4);
                p4[b] += __shfl_down_sync(0xffffffffu, p4[b], 1, 4);
            }

            if (s == 0) {
                const float cb = sb[ll][j];
                const bool bnd = (ll == LPB - 1) && (bid < NB - 1);
#pragma unroll
                for (int b = 0; b < 4; b++) {
                    float a = p4[b] + cb;
                    if (first) a += spre[t * 256 + b * 64 + j];
                    const float h = tanhf(a);
                    if (t == 0) h0s[ll][b * 64 + j] = h;
                    yout[b * 64 + j] = h;
                    if (bnd) {
                        const ull v = (ull)__float_as_uint(h) | (1ull << 32);
                        ull* fp = g_bnd2 + ((size_t)bid * 2 + t) * 256 + b * 64 + j;
                        asm volatile("st.release.gpu.u64 [%0], %1;" ::"l"(fp), "l"(v) : "memory");
                    }
                }
            }
            __syncthreads();
        }
    }

    // ---- output head: last block. h63(t=0) in h0s[1], h63(t=1) in yy[0] ----
    if (bid == NB - 1) {
        for (int idx = tid; idx < 272; idx += 256) {
            const int t = idx / 136;
            const int rem = idx - t * 136;
            const int bb = rem / 34;
            const int o = rem - bb * 34;
            const float* src = (t == 0) ? (h0s[1] + bb * 64) : (yy[0] + bb * 64);
            float a = b_out[o];
            const float4* __restrict__ Wo4 = (const float4*)(W_out + o * 64);
#pragma unroll
            for (int i4 = 0; i4 < 16; i4++) {
                const float4 w = Wo4[i4];
                const float4 v = ((const float4*)src)[i4];
                a += w.x * v.x + w.y * v.y + w.z * v.z + w.w * v.w;
            }
            out[idx] = (a >= 0.f) ? a : 0.4f * a;
        }
    }
}

// ---------------- launch ----------------
extern "C" void kernel_launch(void* const* d_in, const int* in_sizes, int n_in,
                              void* d_out, int out_size) {
    const float* x     = (const float*)d_in[0];
    const float* W_fc  = (const float*)d_in[1];
    const float* b_fc  = (const float*)d_in[2];
    const float* w0    = (const float*)d_in[3];
    const float* b0    = (const float*)d_in[4];
    const float* w1    = (const float*)d_in[5];
    const float* b1    = (const float*)d_in[6];
    const float* w2    = (const float*)d_in[7];
    const float* b2    = (const float*)d_in[8];
    const float* w3    = (const float*)d_in[9];
    const float* b3    = (const float*)d_in[10];
    const float* w4    = (const float*)d_in[11];
    const float* b4    = (const float*)d_in[12];
    const float* w5    = (const float*)d_in[13];
    const float* b5    = (const float*)d_in[14];
    const float* W_ih0 = (const float*)d_in[15];
    const float* b_ih0 = (const float*)d_in[16];
    const float* W_ihr = (const float*)d_in[17];
    const float* b_ihr = (const float*)d_in[18];
    const float* W_hh  = (const float*)d_in[19];
    const float* b_hh  = (const float*)d_in[20];
    const float* W_out = (const float*)d_in[21];
    const float* b_out = (const float*)d_in[22];
    float* out = (float*)d_out;

    fc_kernel<<<512, 256>>>(x, W_fc, b_fc);
    conv_chain_kernel<<<4, 256>>>(w0, b0, w1, b1, w2, b2, w3, b3, w4, b4, w5, b5);
    rnn_pre_kernel<<<64, 256>>>(W_ih0, b_ih0);
    rnn_pipe3_kernel<<<NB, 256>>>(W_ihr, b_ihr, W_hh, b_hh, W_out, b_out, out);
}

// round 7
// speedup vs baseline: 3.7144x; 1.1017x over previous
#include <cuda_runtime.h>
#include <math.h>
#include <stdint.h>

#define NBC  8    // cluster CTAs (portable max)
#define LPBC 8    // layers per CTA

typedef unsigned long long ull;

// ---------------- scratch (no allocations allowed) ----------------
__device__ float g_hfc[4 * 4096];    // FC output, (4, 4096)
__device__ float g_seq[2 * 4096];    // conv-chain output (T=2,B=4,1024)
__device__ float g_pre[2 * 4 * 64];  // layer-0 input projection (+b_ih0)

// ---------------- packed f32x2 helpers (sm_103a) ----------------
__device__ __forceinline__ ull ffma2(ull a, ull b, ull c) {
    ull d;
    asm("fma.rn.f32x2 %0, %1, %2, %3;" : "=l"(d) : "l"(a), "l"(b), "l"(c));
    return d;
}
__device__ __forceinline__ float upk_sum(ull v) {
    float lo, hi;
    asm("mov.b64 {%0,%1}, %2;" : "=f"(lo), "=f"(hi) : "l"(v));
    return lo + hi;
}

// ---------------- cluster / mbarrier helpers ----------------
__device__ __forceinline__ uint32_t ctarank() {
    uint32_t r;
    asm("mov.u32 %0, %%cluster_ctarank;" : "=r"(r));
    return r;
}
__device__ __forceinline__ uint32_t s2u(const void* p) {
    return (uint32_t)__cvta_generic_to_shared(p);
}
__device__ __forceinline__ uint32_t mapa_u32(uint32_t a, uint32_t r) {
    uint32_t o;
    asm("mapa.shared::cluster.u32 %0, %1, %2;" : "=r"(o) : "r"(a), "r"(r));
    return o;
}
__device__ __forceinline__ void st_dsmem_f32(uint32_t addr, float v) {
    asm volatile("st.shared::cluster.f32 [%0], %1;" ::"r"(addr), "f"(v) : "memory");
}
__device__ __forceinline__ void mbar_init(uint32_t addr, uint32_t cnt) {
    asm volatile("mbarrier.init.shared.b64 [%0], %1;" ::"r"(addr), "r"(cnt) : "memory");
}
__device__ __forceinline__ void mbar_arrive_remote(uint32_t addr) {
    asm volatile("mbarrier.arrive.release.cluster.shared::cluster.b64 _, [%0];" ::"r"(addr)
                 : "memory");
}
__device__ __forceinline__ void mbar_wait_acq_cluster(uint32_t addr, uint32_t parity) {
    uint32_t done;
    asm volatile(
        "{\n\t.reg .pred p;\n\t"
        "mbarrier.try_wait.parity.acquire.cluster.shared::cta.b64 p, [%1], %2;\n\t"
        "selp.b32 %0, 1, 0, p;\n\t}"
        : "=r"(done)
        : "r"(addr), "r"(parity)
        : "memory");
    while (!done) {
        asm volatile(
            "{\n\t.reg .pred p;\n\t"
            "mbarrier.try_wait.parity.acquire.cluster.shared::cta.b64 p, [%1], %2, 0x989680;\n\t"
            "selp.b32 %0, 1, 0, p;\n\t}"
            : "=r"(done)
            : "r"(addr), "r"(parity)
            : "memory");
    }
}
__device__ __forceinline__ void cluster_sync_all() {
    asm volatile("barrier.cluster.arrive.aligned;" ::: "memory");
    asm volatile("barrier.cluster.wait.aligned;" ::: "memory");
}

// ---------------- Kernel 1: FC  h = leaky(x @ W^T + b) ----------------
__global__ __launch_bounds__(256) void fc_kernel(const float* __restrict__ x,
                                                 const float* __restrict__ W,
                                                 const float* __restrict__ bias) {
    const int row0 = blockIdx.x * 8;
    const int tid = threadIdx.x;

    float acc[8][4];
#pragma unroll
    for (int r = 0; r < 8; r++)
#pragma unroll
        for (int b = 0; b < 4; b++) acc[r][b] = 0.f;

    const float4* __restrict__ x4 = (const float4*)x;

    for (int c = tid; c < 10240; c += 512) {
        const int c2 = c + 256;
        float4 xv[4], xv2[4];
#pragma unroll
        for (int b = 0; b < 4; b++) {
            xv[b] = x4[b * 10240 + c];
            xv2[b] = x4[b * 10240 + c2];
        }
#pragma unroll
        for (int r = 0; r < 8; r++) {
            const float4* __restrict__ wrow = (const float4*)(W + (size_t)(row0 + r) * 40960);
            const float4 w = __ldcs(wrow + c);
            const float4 w2 = __ldcs(wrow + c2);
#pragma unroll
            for (int b = 0; b < 4; b++) {
                acc[r][b] += w.x * xv[b].x + w.y * xv[b].y + w.z * xv[b].z + w.w * xv[b].w;
                acc[r][b] += w2.x * xv2[b].x + w2.y * xv2[b].y + w2.z * xv2[b].z + w2.w * xv2[b].w;
            }
        }
    }

#pragma unroll
    for (int r = 0; r < 8; r++)
#pragma unroll
        for (int b = 0; b < 4; b++)
#pragma unroll
            for (int off = 16; off; off >>= 1)
                acc[r][b] += __shfl_down_sync(0xffffffffu, acc[r][b], off);

    __shared__ float sred[8][8][4];
    const int lane = tid & 31, wid = tid >> 5;
    if (lane == 0) {
#pragma unroll
        for (int r = 0; r < 8; r++)
#pragma unroll
            for (int b = 0; b < 4; b++) sred[wid][r][b] = acc[r][b];
    }
    __syncthreads();

    if (tid < 32) {
        const int r = tid >> 2, b = tid & 3;
        float s = 0.f;
#pragma unroll
        for (int w = 0; w < 8; w++) s += sred[w][r][b];
        s += bias[row0 + r];
        s = (s >= 0.f) ? s : 0.4f * s;
        g_hfc[b * 4096 + row0 + r] = s;
    }
}

// ---------------- Kernel 2: conv chain + instance norm ----------------
template <int CIN, int HIN, int WIN, int COUT, int HOUT, int WOUT, int STRIDE>
__device__ __forceinline__ void conv_in(const float* __restrict__ in, float* __restrict__ out,
                                        const float* __restrict__ wgt,
                                        const float* __restrict__ bias,
                                        float* smean, float* srstd, int tid) {
    const int S = HOUT * WOUT;
    for (int idx = tid; idx < COUT * S; idx += 256) {
        const int c = idx / S;
        const int rem = idx - c * S;
        const int y = rem / WOUT;
        const int xx = rem - y * WOUT;
        float acc = bias[c];
        for (int ic = 0; ic < CIN; ic++) {
            const float* __restrict__ ip = in + ic * HIN * WIN;
            const float* __restrict__ wp = wgt + (c * CIN + ic) * 9;
#pragma unroll
            for (int dy = 0; dy < 3; dy++) {
                const int yy = y * STRIDE + dy - 1;
                if (yy < 0 || yy >= HIN) continue;
#pragma unroll
                for (int dx = 0; dx < 3; dx++) {
                    const int xs = xx * STRIDE + dx - 1;
                    if (xs < 0 || xs >= WIN) continue;
                    acc += ip[yy * WIN + xs] * wp[dy * 3 + dx];
                }
            }
        }
        out[idx] = acc;
    }
    __syncthreads();

    const int wid = tid >> 5, lane = tid & 31;
    for (int c = wid; c < COUT; c += 8) {
        float s = 0.f, s2 = 0.f;
        for (int e = lane; e < S; e += 32) {
            const float v = out[c * S + e];
            s += v;
            s2 += v * v;
        }
#pragma unroll
        for (int off = 16; off; off >>= 1) {
            s += __shfl_down_sync(0xffffffffu, s, off);
            s2 += __shfl_down_sync(0xffffffffu, s2, off);
        }
        if (lane == 0) {
            const float m = s / (float)S;
            const float var = s2 / (float)S - m * m;
            smean[c] = m;
            srstd[c] = rsqrtf(var + 1e-5f);
        }
    }
    __syncthreads();
    for (int idx = tid; idx < COUT * S; idx += 256) {
        const int c = idx / S;
        out[idx] = (out[idx] - smean[c]) * srstd[c];
    }
    __syncthreads();
}

__global__ __launch_bounds__(256) void conv_chain_kernel(
    const float* __restrict__ w0, const float* __restrict__ b0,
    const float* __restrict__ w1, const float* __restrict__ b1,
    const float* __restrict__ w2, const float* __restrict__ b2,
    const float* __restrict__ w3, const float* __restrict__ b3,
    const float* __restrict__ w4, const float* __restrict__ b4,
    const float* __restrict__ w5, const float* __restrict__ b5) {
    __shared__ float bufA[4096];
    __shared__ float bufB[4096];
    __shared__ float smean[64];
    __shared__ float srstd[64];
    const int n = blockIdx.x;
    const int tid = threadIdx.x;

    for (int i = tid; i < 4096; i += 256) bufA[i] = g_hfc[n * 4096 + i];
    __syncthreads();

    conv_in<1, 4, 1024, 1, 4, 1024, 1>(bufA, bufB, w0, b0, smean, srstd, tid);
    conv_in<1, 4, 1024, 4, 2, 512, 2>(bufB, bufA, w1, b1, smean, srstd, tid);
    conv_in<4, 2, 512, 8, 1, 256, 2>(bufA, bufB, w2, b2, smean, srstd, tid);
    conv_in<8, 1, 256, 16, 1, 128, 2>(bufB, bufA, w3, b3, smean, srstd, tid);
    conv_in<16, 1, 128, 32, 1, 64, 2>(bufA, bufB, w4, b4, smean, srstd, tid);
    conv_in<32, 1, 64, 64, 1, 32, 2>(bufB, bufA, w5, b5, smean, srstd, tid);

    for (int i = tid; i < 2048; i += 256) g_seq[n * 2048 + i] = bufA[i];
}

// ---------------- Kernel 3: layer-0 input projection ----------------
__global__ __launch_bounds__(256) void rnn_pre_kernel(const float* __restrict__ W_ih0,
                                                      const float* __restrict__ b_ih0) {
    const int bid = blockIdx.x;
    const int t = bid >> 5;
    const int b = (bid >> 3) & 3;
    const int jg = bid & 7;
    const int tid = threadIdx.x;
    const int w = tid >> 5, lane = tid & 31;
    const int j = jg * 8 + w;

    const float4* __restrict__ xr = (const float4*)(g_seq + t * 4096 + b * 1024);
    const float4* __restrict__ wr = (const float4*)(W_ih0 + j * 1024);
    float a = 0.f;
#pragma unroll
    for (int i = 0; i < 8; i++) {
        const float4 wv = wr[i * 32 + lane];
        const float4 xv = xr[i * 32 + lane];
        a += wv.x * xv.x + wv.y * xv.y + wv.z * xv.z + wv.w * xv.w;
    }
#pragma unroll
    for (int off = 16; off; off >>= 1) a += __shfl_down_sync(0xffffffffu, a, off);
    if (lane == 0) g_pre[t * 256 + b * 64 + j] = a + b_ih0[j];
}

// ---------------- Kernel 4: cluster-pipelined RNN (DSMEM boundaries) ----------------
// 8 CTAs x 8 layers x 512 threads. thread = (j = tid>>3, s = tid&7).
// Layers 0..3 of each CTA: weights in registers; layers 4..7: padded smem.
// Dynamic smem: 8 matrices * 2112 u64 (stride-33 rows -> conflict-free LDS.64).
#define WSM_U64 (8 * 2112)

__global__ __launch_bounds__(512, 1) __cluster_dims__(NBC, 1, 1) void rnn_pipe4_kernel(
    const float* __restrict__ W_ihr, const float* __restrict__ b_ihr,
    const float* __restrict__ W_hh, const float* __restrict__ b_hh,
    const float* __restrict__ W_out, const float* __restrict__ b_out,
    float* __restrict__ out) {
    extern __shared__ ull wsm[];
    __shared__ float yy[2][256];
    __shared__ float inbox[2][256];
    __shared__ float h0s[LPBC][256];
    __shared__ float sb[LPBC][64];
    __shared__ float spre[512];
    __shared__ __align__(8) ull sbar[2];

    const uint32_t rank = ctarank();
    const int tid = threadIdx.x;
    const int j = tid >> 3;  // output row 0..63
    const int s = tid & 7;   // k-segment 0..7 (8 floats)
    const int l0 = (int)rank * LPBC;

    // ---- init boundary barriers (64 producer arrivals each) ----
    if (tid == 0) {
        mbar_init(s2u(&sbar[0]), 64);
        mbar_init(s2u(&sbar[1]), 64);
    }

    // ---- preload: registers (layers 0..3) ----
    ull wi[4][4], wh[4][4];
#pragma unroll
    for (int ll = 0; ll < 4; ll++) {
        const int l = l0 + ll;
        const ull* ph = (const ull*)(W_hh + (size_t)l * 4096 + j * 64 + s * 8);
#pragma unroll
        for (int i = 0; i < 4; i++) wh[ll][i] = ph[i];
        if (l >= 1) {
            const ull* pi = (const ull*)(W_ihr + (size_t)(l - 1) * 4096 + j * 64 + s * 8);
#pragma unroll
            for (int i = 0; i < 4; i++) wi[ll][i] = pi[i];
        } else {
#pragma unroll
            for (int i = 0; i < 4; i++) wi[ll][i] = 0ull;
        }
    }
    // ---- preload: smem (layers 4..7), padded stride 33 u64 ----
    for (int m = 0; m < 8; m++) {
        const int ll = 4 + (m >> 1);
        const int l = l0 + ll;
        const ull* src = (m & 1) ? (const ull*)(W_hh + (size_t)l * 4096)
                                 : (const ull*)(W_ihr + (size_t)(l - 1) * 4096);
        ull* dst = wsm + m * 2112;
        for (int idx = tid; idx < 2048; idx += 512) {
            const int jj = idx >> 5, kp = idx & 31;
            dst[jj * 33 + kp] = src[idx];
        }
    }
    if (tid < 64) {
#pragma unroll
        for (int ll = 0; ll < LPBC; ll++) {
            const int l = l0 + ll;
            sb[ll][tid] = b_hh[l * 64 + tid] + (l >= 1 ? b_ihr[(l - 1) * 64 + tid] : 0.f);
        }
    }
    if (rank == 0 && tid < 512) spre[tid] = g_pre[tid];
    __syncthreads();
    cluster_sync_all();  // barriers + weights visible cluster-wide

    const uint32_t mybar0 = s2u(&sbar[0]);
    const uint32_t mybar1 = s2u(&sbar[1]);

    for (int t = 0; t < 2; t++) {
        if (rank > 0) mbar_wait_acq_cluster(t == 0 ? mybar0 : mybar1, 0);

#pragma unroll
        for (int ll = 0; ll < LPBC; ll++) {
            const bool first = (rank == 0 && ll == 0);
            const float* yin = (ll == 0) ? inbox[t] : yy[ll & 1];
            float* yout = yy[(ll + 1) & 1];

            ull acc[4] = {0ull, 0ull, 0ull, 0ull};
            if (!first) {
#pragma unroll
                for (int i = 0; i < 4; i++) {
                    const ull w = (ll < 4) ? wi[ll][i]
                                           : wsm[((ll - 4) * 2) * 2112 + j * 33 + s * 4 + i];
#pragma unroll
                    for (int b = 0; b < 4; b++) {
                        const ull yv = ((const ull*)(yin + b * 64 + s * 8))[i];
                        acc[b] = ffma2(w, yv, acc[b]);
                    }
                }
            }
            if (t == 1) {
#pragma unroll
                for (int i = 0; i < 4; i++) {
                    const ull w = (ll < 4) ? wh[ll][i]
                                           : wsm[((ll - 4) * 2 + 1) * 2112 + j * 33 + s * 4 + i];
#pragma unroll
                    for (int b = 0; b < 4; b++) {
                        const ull hv = ((const ull*)(h0s[ll] + b * 64 + s * 8))[i];
                        acc[b] = ffma2(w, hv, acc[b]);
                    }
                }
            }

            float p4[4];
#pragma unroll
            for (int b = 0; b < 4; b++) {
                p4[b] = upk_sum(acc[b]);
                p4[b] += __shfl_down_sync(0xffffffffu, p4[b], 4, 8);
                p4[b] += __shfl_down_sync(0xffffffffu, p4[b], 2, 8);
                p4[b] += __shfl_down_sync(0xffffffffu, p4[b], 1, 8);
            }

            if (s == 0) {
                const float cb = sb[ll][j];
                const bool bnd = (ll == LPBC - 1) && (rank < NBC - 1);
#pragma unroll
                for (int b = 0; b < 4; b++) {
                    float a = p4[b] + cb;
                    if (first) a += spre[t * 256 + b * 64 + j];
                    const float h = tanhf(a);
                    if (t == 0) h0s[ll][b * 64 + j] = h;
                    yout[b * 64 + j] = h;
                    if (bnd) {
                        const uint32_t laddr = s2u(&inbox[t][b * 64 + j]);
                        st_dsmem_f32(mapa_u32(laddr, rank + 1), h);
                    }
                }
                if (bnd) {
                    const uint32_t rbar = mapa_u32(t == 0 ? mybar0 : mybar1, rank + 1);
                    mbar_arrive_remote(rbar);
                }
            }
            __syncthreads();
        }
    }

    // ---- output head: last CTA. h63(t=0) in h0s[7], h63(t=1) in yy[0] ----
    if (rank == NBC - 1) {
        for (int idx = tid; idx < 272; idx += 512) {
            const int t = idx / 136;
            const int rem = idx - t * 136;
            const int bb = rem / 34;
            const int o = rem - bb * 34;
            const float* src = (t == 0) ? (h0s[LPBC - 1] + bb * 64) : (yy[0] + bb * 64);
            float a = b_out[o];
            const float4* __restrict__ Wo4 = (const float4*)(W_out + o * 64);
#pragma unroll
            for (int i4 = 0; i4 < 16; i4++) {
                const float4 w = Wo4[i4];
                const float4 v = ((const float4*)src)[i4];
                a += w.x * v.x + w.y * v.y + w.z * v.z + w.w * v.w;
            }
            out[idx] = (a >= 0.f) ? a : 0.4f * a;
        }
    }

    cluster_sync_all();  // no CTA exits while peers may touch its smem
}

// ---------------- launch ----------------
extern "C" void kernel_launch(void* const* d_in, const int* in_sizes, int n_in,
                              void* d_out, int out_size) {
    const float* x     = (const float*)d_in[0];
    const float* W_fc  = (const float*)d_in[1];
    const float* b_fc  = (const float*)d_in[2];
    const float* w0    = (const float*)d_in[3];
    const float* b0    = (const float*)d_in[4];
    const float* w1    = (const float*)d_in[5];
    const float* b1    = (const float*)d_in[6];
    const float* w2    = (const float*)d_in[7];
    const float* b2    = (const float*)d_in[8];
    const float* w3    = (const float*)d_in[9];
    const float* b3    = (const float*)d_in[10];
    const float* w4    = (const float*)d_in[11];
    const float* b4    = (const float*)d_in[12];
    const float* w5    = (const float*)d_in[13];
    const float* b5    = (const float*)d_in[14];
    const float* W_ih0 = (const float*)d_in[15];
    const float* b_ih0 = (const float*)d_in[16];
    const float* W_ihr = (const float*)d_in[17];
    const float* b_ihr = (const float*)d_in[18];
    const float* W_hh  = (const float*)d_in[19];
    const float* b_hh  = (const float*)d_in[20];
    const float* W_out = (const float*)d_in[21];
    const float* b_out = (const float*)d_in[22];
    float* out = (float*)d_out;

    const size_t wsm_bytes = (size_t)WSM_U64 * sizeof(ull);  // 135168 B

    cudaStreamCaptureStatus cap = cudaStreamCaptureStatusNone;
    cudaStreamIsCapturing(cudaStreamLegacy, &cap);
    if (cap == cudaStreamCaptureStatusNone) {
        cudaFuncSetAttribute(rnn_pipe4_kernel,
                             cudaFuncAttributeMaxDynamicSharedMemorySize, (int)wsm_bytes);
    }

    fc_kernel<<<512, 256>>>(x, W_fc, b_fc);
    conv_chain_kernel<<<4, 256>>>(w0, b0, w1, b1, w2, b2, w3, b3, w4, b4, w5, b5);
    rnn_pre_kernel<<<64, 256>>>(W_ih0, b_ih0);
    rnn_pipe4_kernel<<<NBC, 512, wsm_bytes>>>(W_ihr, b_ihr, W_hh, b_hh, W_out, b_out, out);
}

// round 9
// speedup vs baseline: 3.8144x; 1.0269x over previous
#include <cuda_runtime.h>
#include <math.h>
#include <stdint.h>

#define NBC  8    // cluster CTAs (portable max)
#define LPBC 8    // layers per CTA

typedef unsigned long long ull;

// ---------------- scratch (no allocations allowed) ----------------
__device__ float g_hfc[4 * 4096];    // FC output, (4, 4096)
__device__ float g_seq[2 * 4096];    // conv-chain output (T=2,B=4,1024)
__device__ float g_pre[2 * 4 * 64];  // layer-0 input projection (+b_ih0)

// ---------------- packed f32x2 helpers (sm_103a) ----------------
__device__ __forceinline__ ull ffma2(ull a, ull b, ull c) {
    ull d;
    asm("fma.rn.f32x2 %0, %1, %2, %3;" : "=l"(d) : "l"(a), "l"(b), "l"(c));
    return d;
}
__device__ __forceinline__ float upk_sum(ull v) {
    float lo, hi;
    asm("mov.b64 {%0,%1}, %2;" : "=f"(lo), "=f"(hi) : "l"(v));
    return lo + hi;
}

// fast tanh: (e^{2x}-1)/(e^{2x}+1), MUFU-only. |err| ~1e-7 rel, saturates cleanly.
__device__ __forceinline__ float ftanh(float x) {
    x = fminf(fmaxf(x, -9.f), 9.f);
    const float e = __expf(2.f * x);
    return __fdividef(e - 1.f, e + 1.f);
}

// ---------------- cluster / mbarrier helpers ----------------
__device__ __forceinline__ uint32_t ctarank() {
    uint32_t r;
    asm("mov.u32 %0, %%cluster_ctarank;" : "=r"(r));
    return r;
}
__device__ __forceinline__ uint32_t s2u(const void* p) {
    return (uint32_t)__cvta_generic_to_shared(p);
}
__device__ __forceinline__ uint32_t mapa_u32(uint32_t a, uint32_t r) {
    uint32_t o;
    asm("mapa.shared::cluster.u32 %0, %1, %2;" : "=r"(o) : "r"(a), "r"(r));
    return o;
}
__device__ __forceinline__ void st_dsmem_f32(uint32_t addr, float v) {
    asm volatile("st.shared::cluster.f32 [%0], %1;" ::"r"(addr), "f"(v) : "memory");
}
__device__ __forceinline__ void mbar_init(uint32_t addr, uint32_t cnt) {
    asm volatile("mbarrier.init.shared.b64 [%0], %1;" ::"r"(addr), "r"(cnt) : "memory");
}
__device__ __forceinline__ void mbar_arrive_remote(uint32_t addr) {
    asm volatile("mbarrier.arrive.release.cluster.shared::cluster.b64 _, [%0];" ::"r"(addr)
                 : "memory");
}
__device__ __forceinline__ void mbar_wait_acq_cluster(uint32_t addr, uint32_t parity) {
    uint32_t done;
    asm volatile(
        "{\n\t.reg .pred p;\n\t"
        "mbarrier.try_wait.parity.acquire.cluster.shared::cta.b64 p, [%1], %2;\n\t"
        "selp.b32 %0, 1, 0, p;\n\t}"
        : "=r"(done)
        : "r"(addr), "r"(parity)
        : "memory");
    while (!done) {
        asm volatile(
            "{\n\t.reg .pred p;\n\t"
            "mbarrier.try_wait.parity.acquire.cluster.shared::cta.b64 p, [%1], %2, 0x989680;\n\t"
            "selp.b32 %0, 1, 0, p;\n\t}"
            : "=r"(done)
            : "r"(addr), "r"(parity)
            : "memory");
    }
}
__device__ __forceinline__ void cluster_sync_all() {
    asm volatile("barrier.cluster.arrive.aligned;" ::: "memory");
    asm volatile("barrier.cluster.wait.aligned;" ::: "memory");
}

// ---------------- Kernel 1: FC  h = leaky(x @ W^T + b) ----------------
__global__ __launch_bounds__(256) void fc_kernel(const float* __restrict__ x,
                                                 const float* __restrict__ W,
                                                 const float* __restrict__ bias) {
    const int row0 = blockIdx.x * 8;
    const int tid = threadIdx.x;

    float acc[8][4];
#pragma unroll
    for (int r = 0; r < 8; r++)
#pragma unroll
        for (int b = 0; b < 4; b++) acc[r][b] = 0.f;

    const float4* __restrict__ x4 = (const float4*)x;

    for (int c = tid; c < 10240; c += 512) {
        const int c2 = c + 256;
        float4 xv[4], xv2[4];
#pragma unroll
        for (int b = 0; b < 4; b++) {
            xv[b] = x4[b * 10240 + c];
            xv2[b] = x4[b * 10240 + c2];
        }
#pragma unroll
        for (int r = 0; r < 8; r++) {
            const float4* __restrict__ wrow = (const float4*)(W + (size_t)(row0 + r) * 40960);
            const float4 w = __ldcs(wrow + c);
            const float4 w2 = __ldcs(wrow + c2);
#pragma unroll
            for (int b = 0; b < 4; b++) {
                acc[r][b] += w.x * xv[b].x + w.y * xv[b].y + w.z * xv[b].z + w.w * xv[b].w;
                acc[r][b] += w2.x * xv2[b].x + w2.y * xv2[b].y + w2.z * xv2[b].z + w2.w * xv2[b].w;
            }
        }
    }

#pragma unroll
    for (int r = 0; r < 8; r++)
#pragma unroll
        for (int b = 0; b < 4; b++)
#pragma unroll
            for (int off = 16; off; off >>= 1)
                acc[r][b] += __shfl_down_sync(0xffffffffu, acc[r][b], off);

    __shared__ float sred[8][8][4];
    const int lane = tid & 31, wid = tid >> 5;
    if (lane == 0) {
#pragma unroll
        for (int r = 0; r < 8; r++)
#pragma unroll
            for (int b = 0; b < 4; b++) sred[wid][r][b] = acc[r][b];
    }
    __syncthreads();

    if (tid < 32) {
        const int r = tid >> 2, b = tid & 3;
        float s = 0.f;
#pragma unroll
        for (int w = 0; w < 8; w++) s += sred[w][r][b];
        s += bias[row0 + r];
        s = (s >= 0.f) ? s : 0.4f * s;
        g_hfc[b * 4096 + row0 + r] = s;
    }
}

// ---------------- Kernel 2: conv chain + instance norm ----------------
template <int CIN, int HIN, int WIN, int COUT, int HOUT, int WOUT, int STRIDE>
__device__ __forceinline__ void conv_in(const float* __restrict__ in, float* __restrict__ out,
                                        const float* __restrict__ wgt,
                                        const float* __restrict__ bias,
                                        float* smean, float* srstd, int tid) {
    const int S = HOUT * WOUT;
    for (int idx = tid; idx < COUT * S; idx += 256) {
        const int c = idx / S;
        const int rem = idx - c * S;
        const int y = rem / WOUT;
        const int xx = rem - y * WOUT;
        float acc = bias[c];
        for (int ic = 0; ic < CIN; ic++) {
            const float* __restrict__ ip = in + ic * HIN * WIN;
            const float* __restrict__ wp = wgt + (c * CIN + ic) * 9;
#pragma unroll
            for (int dy = 0; dy < 3; dy++) {
                const int yy = y * STRIDE + dy - 1;
                if (yy < 0 || yy >= HIN) continue;
#pragma unroll
                for (int dx = 0; dx < 3; dx++) {
                    const int xs = xx * STRIDE + dx - 1;
                    if (xs < 0 || xs >= WIN) continue;
                    acc += ip[yy * WIN + xs] * wp[dy * 3 + dx];
                }
            }
        }
        out[idx] = acc;
    }
    __syncthreads();

    const int wid = tid >> 5, lane = tid & 31;
    for (int c = wid; c < COUT; c += 8) {
        float s = 0.f, s2 = 0.f;
        for (int e = lane; e < S; e += 32) {
            const float v = out[c * S + e];
            s += v;
            s2 += v * v;
        }
#pragma unroll
        for (int off = 16; off; off >>= 1) {
            s += __shfl_down_sync(0xffffffffu, s, off);
            s2 += __shfl_down_sync(0xffffffffu, s2, off);
        }
        if (lane == 0) {
            const float m = s / (float)S;
            const float var = s2 / (float)S - m * m;
            smean[c] = m;
            srstd[c] = rsqrtf(var + 1e-5f);
        }
    }
    __syncthreads();
    for (int idx = tid; idx < COUT * S; idx += 256) {
        const int c = idx / S;
        out[idx] = (out[idx] - smean[c]) * srstd[c];
    }
    __syncthreads();
}

__global__ __launch_bounds__(256) void conv_chain_kernel(
    const float* __restrict__ w0, const float* __restrict__ b0,
    const float* __restrict__ w1, const float* __restrict__ b1,
    const float* __restrict__ w2, const float* __restrict__ b2,
    const float* __restrict__ w3, const float* __restrict__ b3,
    const float* __restrict__ w4, const float* __restrict__ b4,
    const float* __restrict__ w5, const float* __restrict__ b5) {
    __shared__ float bufA[4096];
    __shared__ float bufB[4096];
    __shared__ float smean[64];
    __shared__ float srstd[64];
    const int n = blockIdx.x;
    const int tid = threadIdx.x;

    for (int i = tid; i < 4096; i += 256) bufA[i] = g_hfc[n * 4096 + i];
    __syncthreads();

    conv_in<1, 4, 1024, 1, 4, 1024, 1>(bufA, bufB, w0, b0, smean, srstd, tid);
    conv_in<1, 4, 1024, 4, 2, 512, 2>(bufB, bufA, w1, b1, smean, srstd, tid);
    conv_in<4, 2, 512, 8, 1, 256, 2>(bufA, bufB, w2, b2, smean, srstd, tid);
    conv_in<8, 1, 256, 16, 1, 128, 2>(bufB, bufA, w3, b3, smean, srstd, tid);
    conv_in<16, 1, 128, 32, 1, 64, 2>(bufA, bufB, w4, b4, smean, srstd, tid);
    conv_in<32, 1, 64, 64, 1, 32, 2>(bufB, bufA, w5, b5, smean, srstd, tid);

    for (int i = tid; i < 2048; i += 256) g_seq[n * 2048 + i] = bufA[i];
}

// ---------------- Kernel 3: layer-0 input projection ----------------
__global__ __launch_bounds__(256) void rnn_pre_kernel(const float* __restrict__ W_ih0,
                                                      const float* __restrict__ b_ih0) {
    const int bid = blockIdx.x;
    const int t = bid >> 5;
    const int b = (bid >> 3) & 3;
    const int jg = bid & 7;
    const int tid = threadIdx.x;
    const int w = tid >> 5, lane = tid & 31;
    const int j = jg * 8 + w;

    const float4* __restrict__ xr = (const float4*)(g_seq + t * 4096 + b * 1024);
    const float4* __restrict__ wr = (const float4*)(W_ih0 + j * 1024);
    float a = 0.f;
#pragma unroll
    for (int i = 0; i < 8; i++) {
        const float4 wv = wr[i * 32 + lane];
        const float4 xv = xr[i * 32 + lane];
        a += wv.x * xv.x + wv.y * xv.y + wv.z * xv.z + wv.w * xv.w;
    }
#pragma unroll
    for (int off = 16; off; off >>= 1) a += __shfl_down_sync(0xffffffffu, a, off);
    if (lane == 0) g_pre[t * 256 + b * 64 + j] = a + b_ih0[j];
}

// ---------------- Kernel 4: cluster-pipelined RNN (DSMEM boundaries) ----------------
// 8 CTAs x 8 layers x 512 threads. thread = (j = tid>>3, s = tid&7).
// Layers 0..3: weights in registers; layers 4..7: padded smem (stride 33 u64).
#define WSM_U64 (8 * 2112)

__global__ __launch_bounds__(512, 1) __cluster_dims__(NBC, 1, 1) void rnn_pipe5_kernel(
    const float* __restrict__ W_ihr, const float* __restrict__ b_ihr,
    const float* __restrict__ W_hh, const float* __restrict__ b_hh,
    const float* __restrict__ W_out, const float* __restrict__ b_out,
    float* __restrict__ out) {
    extern __shared__ ull wsm[];
    __shared__ float yy[2][256];
    __shared__ float inbox[2][256];
    __shared__ float h0s[LPBC][256];
    __shared__ float sb[LPBC][64];
    __shared__ float spre[512];
    __shared__ __align__(8) ull sbar[2];

    const uint32_t rank = ctarank();
    const int tid = threadIdx.x;
    const int j = tid >> 3;  // output row 0..63
    const int s = tid & 7;   // k-segment 0..7 (8 floats)
    const int l0 = (int)rank * LPBC;

    if (tid == 0) {
        mbar_init(s2u(&sbar[0]), 256);
        mbar_init(s2u(&sbar[1]), 256);
    }

    // ---- preload: registers (layers 0..3) ----
    ull wi[4][4], wh[4][4];
#pragma unroll
    for (int ll = 0; ll < 4; ll++) {
        const int l = l0 + ll;
        const ull* ph = (const ull*)(W_hh + (size_t)l * 4096 + j * 64 + s * 8);
#pragma unroll
        for (int i = 0; i < 4; i++) wh[ll][i] = ph[i];
        if (l >= 1) {
            const ull* pi = (const ull*)(W_ihr + (size_t)(l - 1) * 4096 + j * 64 + s * 8);
#pragma unroll
            for (int i = 0; i < 4; i++) wi[ll][i] = pi[i];
        } else {
#pragma unroll
            for (int i = 0; i < 4; i++) wi[ll][i] = 0ull;
        }
    }
    // ---- preload: smem (layers 4..7) ----
    for (int m = 0; m < 8; m++) {
        const int ll = 4 + (m >> 1);
        const int l = l0 + ll;
        const ull* src = (m & 1) ? (const ull*)(W_hh + (size_t)l * 4096)
                                 : (const ull*)(W_ihr + (size_t)(l - 1) * 4096);
        ull* dst = wsm + m * 2112;
        for (int idx = tid; idx < 2048; idx += 512) {
            const int jj = idx >> 5, kp = idx & 31;
            dst[jj * 33 + kp] = src[idx];
        }
    }
    if (tid < 64) {
#pragma unroll
        for (int ll = 0; ll < LPBC; ll++) {
            const int l = l0 + ll;
            sb[ll][tid] = b_hh[l * 64 + tid] + (l >= 1 ? b_ihr[(l - 1) * 64 + tid] : 0.f);
        }
    }
    if (rank == 0 && tid < 512) spre[tid] = g_pre[tid];
    __syncthreads();
    cluster_sync_all();

    const uint32_t mybar0 = s2u(&sbar[0]);
    const uint32_t mybar1 = s2u(&sbar[1]);

    for (int t = 0; t < 2; t++) {
        if (rank > 0) mbar_wait_acq_cluster(t == 0 ? mybar0 : mybar1, 0);

#pragma unroll
        for (int ll = 0; ll < LPBC; ll++) {
            const bool first = (rank == 0 && ll == 0);
            const float* yin = (ll == 0) ? inbox[t] : yy[ll & 1];
            float* yout = yy[(ll + 1) & 1];

            ull acc[4] = {0ull, 0ull, 0ull, 0ull};
            if (!first) {
#pragma unroll
                for (int i = 0; i < 4; i++) {
                    const ull w = (ll < 4) ? wi[ll][i]
                                           : wsm[((ll - 4) * 2) * 2112 + j * 33 + s * 4 + i];
#pragma unroll
                    for (int b = 0; b < 4; b++) {
                        const ull yv = ((const ull*)(yin + b * 64 + s * 8))[i];
                        acc[b] = ffma2(w, yv, acc[b]);
                    }
                }
            }
            if (t == 1) {
#pragma unroll
                for (int i = 0; i < 4; i++) {
                    const ull w = (ll < 4) ? wh[ll][i]
                                           : wsm[((ll - 4) * 2 + 1) * 2112 + j * 33 + s * 4 + i];
#pragma unroll
                    for (int b = 0; b < 4; b++) {
                        const ull hv = ((const ull*)(h0s[ll] + b * 64 + s * 8))[i];
                        acc[b] = ffma2(w, hv, acc[b]);
                    }
                }
            }

            // butterfly: every lane of the 8-lane group ends with all 4 batch sums
            float p4[4];
#pragma unroll
            for (int b = 0; b < 4; b++) {
                p4[b] = upk_sum(acc[b]);
                p4[b] += __shfl_xor_sync(0xffffffffu, p4[b], 1, 8);
                p4[b] += __shfl_xor_sync(0xffffffffu, p4[b], 2, 8);
                p4[b] += __shfl_xor_sync(0xffffffffu, p4[b], 4, 8);
            }

            // lanes s=0..3 each finish one batch: tanh + stores spread 4-wide
            if (s < 4) {
                const int b = s;
                float a = p4[b] + sb[ll][j];
                if (first) a += spre[t * 256 + b * 64 + j];
                const float h = ftanh(a);
                if (t == 0) h0s[ll][b * 64 + j] = h;
                yout[b * 64 + j] = h;
                if ((ll == LPBC - 1) && (rank < NBC - 1)) {
                    const uint32_t laddr = s2u(&inbox[t][b * 64 + j]);
                    st_dsmem_f32(mapa_u32(laddr, rank + 1), h);
                    mbar_arrive_remote(mapa_u32(t == 0 ? mybar0 : mybar1, rank + 1));
                }
            }
            __syncthreads();
        }
    }

    // ---- output head: last CTA. h63(t=0) in h0s[7], h63(t=1) in yy[0] ----
    if (rank == NBC - 1) {
        for (int idx = tid; idx < 272; idx += 512) {
            const int t = idx / 136;
            const int rem = idx - t * 136;
            const int bb = rem / 34;
            const int o = rem - bb * 34;
            const float* src = (t == 0) ? (h0s[LPBC - 1] + bb * 64) : (yy[0] + bb * 64);
            float a = b_out[o];
            const float4* __restrict__ Wo4 = (const float4*)(W_out + o * 64);
#pragma unroll
            for (int i4 = 0; i4 < 16; i4++) {
                const float4 w = Wo4[i4];
                const float4 v = ((const float4*)src)[i4];
                a += w.x * v.x + w.y * v.y + w.z * v.z + w.w * v.w;
            }
            out[idx] = (a >= 0.f) ? a : 0.4f * a;
        }
    }

    cluster_sync_all();  // no CTA exits while peers may touch its smem
}

// ---------------- launch ----------------
extern "C" void kernel_launch(void* const* d_in, const int* in_sizes, int n_in,
                              void* d_out, int out_size) {
    const float* x     = (const float*)d_in[0];
    const float* W_fc  = (const float*)d_in[1];
    const float* b_fc  = (const float*)d_in[2];
    const float* w0    = (const float*)d_in[3];
    const float* b0    = (const float*)d_in[4];
    const float* w1    = (const float*)d_in[5];
    const float* b1    = (const float*)d_in[6];
    const float* w2    = (const float*)d_in[7];
    const float* b2    = (const float*)d_in[8];
    const float* w3    = (const float*)d_in[9];
    const float* b3    = (const float*)d_in[10];
    const float* w4    = (const float*)d_in[11];
    const float* b4    = (const float*)d_in[12];
    const float* w5    = (const float*)d_in[13];
    const float* b5    = (const float*)d_in[14];
    const float* W_ih0 = (const float*)d_in[15];
    const float* b_ih0 = (const float*)d_in[16];
    const float* W_ihr = (const float*)d_in[17];
    const float* b_ihr = (const float*)d_in[18];
    const float* W_hh  = (const float*)d_in[19];
    const float* b_hh  = (const float*)d_in[20];
    const float* W_out = (const float*)d_in[21];
    const float* b_out = (const float*)d_in[22];
    float* out = (float*)d_out;

    const size_t wsm_bytes = (size_t)WSM_U64 * sizeof(ull);  // 135168 B

    cudaStreamCaptureStatus cap = cudaStreamCaptureStatusNone;
    cudaStreamIsCapturing(cudaStreamLegacy, &cap);
    if (cap == cudaStreamCaptureStatusNone) {
        cudaFuncSetAttribute(rnn_pipe5_kernel,
                             cudaFuncAttributeMaxDynamicSharedMemorySize, (int)wsm_bytes);
    }

    fc_kernel<<<512, 256>>>(x, W_fc, b_fc);
    conv_chain_kernel<<<4, 256>>>(w0, b0, w1, b1, w2, b2, w3, b3, w4, b4, w5, b5);
    rnn_pre_kernel<<<64, 256>>>(W_ih0, b_ih0);
    rnn_pipe5_kernel<<<NBC, 512, wsm_bytes>>>(W_ihr, b_ihr, W_hh, b_hh, W_out, b_out, out);
}